// round 1
// baseline (speedup 1.0000x reference)
#include <cuda_runtime.h>
#include <math.h>

// ---------------- problem constants ----------------
#define CB   4
#define CT   5
#define CC   512
#define CHW  1024        // H*W = 32*32
#define CBT  20          // B*T
#define CG   32          // groupnorm groups
#define CPG  16          // channels per group
#define GEPS 1e-6f
#define TTC  (CT*CC)     // 2560, row stride of pixel-major temporal buffers
#define SCALE 0.04419417382415922f   // 512^-0.5

// ---------------- scratch (device globals; no allocations allowed) ----------
static __device__ float g_hn[(size_t)CBT*CC*CHW];       // 42 MB
static __device__ float g_q [(size_t)CBT*CC*CHW];
static __device__ float g_k [(size_t)CBT*CC*CHW];
static __device__ float g_v [(size_t)CBT*CC*CHW];
static __device__ float g_att[(size_t)CBT*CHW*CHW];     // 80 MB
static __device__ float g_hsp[(size_t)CBT*CC*CHW];
static __device__ float g_spatio[(size_t)CBT*CC*CHW];

// ---------------- warp helpers ----------------
static __inline__ __device__ float warpSum(float v) {
    #pragma unroll
    for (int o = 16; o > 0; o >>= 1) v += __shfl_xor_sync(0xffffffffu, v, o);
    return v;
}
static __inline__ __device__ float warpMax(float v) {
    #pragma unroll
    for (int o = 16; o > 0; o >>= 1) v = fmaxf(v, __shfl_xor_sync(0xffffffffu, v, o));
    return v;
}

// ---------------- GroupNorm: one block per (n, g); group span is contiguous --
__global__ __launch_bounds__(256) void groupnorm_kernel(
    const float* __restrict__ x, float* __restrict__ out,
    const float* __restrict__ gamma, const float* __restrict__ beta)
{
    const int GSZ = CPG * CHW;                 // 16384 contiguous floats
    int n = blockIdx.x / CG, g = blockIdx.x % CG;
    size_t base = (size_t)n * CC * CHW + (size_t)g * GSZ;
    int tid = threadIdx.x, lane = tid & 31, wid = tid >> 5;

    float s = 0.f, s2 = 0.f;
    for (int i = tid; i < GSZ; i += 256) {
        float v = x[base + i];
        s += v; s2 += v * v;
    }
    __shared__ float rs[8], rs2[8];
    s = warpSum(s); s2 = warpSum(s2);
    if (lane == 0) { rs[wid] = s; rs2[wid] = s2; }
    __syncthreads();
    if (tid == 0) {
        float S = 0.f, S2 = 0.f;
        #pragma unroll
        for (int w = 0; w < 8; w++) { S += rs[w]; S2 += rs2[w]; }
        rs[0] = S; rs2[0] = S2;
    }
    __syncthreads();
    float mu = rs[0] / (float)GSZ;
    float var = rs2[0] / (float)GSZ - mu * mu;
    float rstd = rsqrtf(var + GEPS);

    for (int i = tid; i < GSZ; i += 256) {
        int c = g * CPG + (i >> 10);           // i / CHW
        out[base + i] = (x[base + i] - mu) * rstd * gamma[c] + beta[c];
    }
}

// ---------------- generic tiled FP32 GEMM -----------------------------------
// C[m,n] = alpha * sum_k Aop[m,k]*Bop[k,n] (+bias[m]) (+resid)
//   ta=0: A[m*lda+k]   ta=1: A[k*lda+m]
//   tb=0: B[k*ldb+n]   tb=1: B[n*ldb+k]
//   bmode=1: temporal pixel-major B batch offset; cmode=1: pixel-major C store
#define BM 64
#define BN 64
#define BKK 16

__global__ __launch_bounds__(256) void gemm_kernel(
    const float* __restrict__ A, const float* __restrict__ B, float* __restrict__ Cm,
    const float* __restrict__ bias, const float* __restrict__ resid,
    int N, int K, int lda, int ldb,
    long sA, long sB, long sC, long sR,
    float alpha, int ta, int tb, int bmode, int cmode)
{
    __shared__ float As[BKK][BM + 1];
    __shared__ float Bs[BKK][BN + 1];
    int tid = threadIdx.x;
    int tx = tid & 15, ty = tid >> 4;
    int m0 = blockIdx.x * BM, n0 = blockIdx.y * BN;
    int bz = blockIdx.z;

    size_t aoff = (size_t)bz * sA;
    size_t boff = (bmode == 0) ? (size_t)bz * sB
                               : (size_t)(bz / CT) * ((size_t)CHW * TTC) + (size_t)(bz % CT) * CC;

    float acc[4][4] = {};

    for (int k0 = 0; k0 < K; k0 += BKK) {
        if (ta == 0) {
            int m = tid >> 2, kq = (tid & 3) << 2;
            float4 av = *(const float4*)(A + aoff + (size_t)(m0 + m) * lda + (k0 + kq));
            As[kq + 0][m] = av.x; As[kq + 1][m] = av.y; As[kq + 2][m] = av.z; As[kq + 3][m] = av.w;
        } else {
            int k = tid >> 4, mq = (tid & 15) << 2;
            float4 av = *(const float4*)(A + aoff + (size_t)(k0 + k) * lda + (m0 + mq));
            As[k][mq + 0] = av.x; As[k][mq + 1] = av.y; As[k][mq + 2] = av.z; As[k][mq + 3] = av.w;
        }
        if (tb == 0) {
            int k = tid >> 4, nq = (tid & 15) << 2;
            float4 bv = *(const float4*)(B + boff + (size_t)(k0 + k) * ldb + (n0 + nq));
            Bs[k][nq + 0] = bv.x; Bs[k][nq + 1] = bv.y; Bs[k][nq + 2] = bv.z; Bs[k][nq + 3] = bv.w;
        } else {
            int n = tid >> 2, kq = (tid & 3) << 2;
            float4 bv = *(const float4*)(B + boff + (size_t)(n0 + n) * ldb + (k0 + kq));
            Bs[kq + 0][n] = bv.x; Bs[kq + 1][n] = bv.y; Bs[kq + 2][n] = bv.z; Bs[kq + 3][n] = bv.w;
        }
        __syncthreads();
        #pragma unroll
        for (int k = 0; k < BKK; k++) {
            float ra[4], rb[4];
            #pragma unroll
            for (int i = 0; i < 4; i++) ra[i] = As[k][ty * 4 + i];
            #pragma unroll
            for (int j = 0; j < 4; j++) rb[j] = Bs[k][tx * 4 + j];
            #pragma unroll
            for (int i = 0; i < 4; i++)
                #pragma unroll
                for (int j = 0; j < 4; j++)
                    acc[i][j] = fmaf(ra[i], rb[j], acc[i][j]);
        }
        __syncthreads();
    }

    if (cmode == 0) {
        size_t coff = (size_t)bz * sC;
        size_t roff = (size_t)bz * sR;
        #pragma unroll
        for (int i = 0; i < 4; i++) {
            int m = m0 + ty * 4 + i;
            float bv = bias ? bias[m] : 0.f;
            #pragma unroll
            for (int j = 0; j < 4; j++) {
                int n = n0 + tx * 4 + j;
                float v = acc[i][j] * alpha + bv;
                if (resid) v += resid[roff + (size_t)m * N + n];
                Cm[coff + (size_t)m * N + n] = v;
            }
        }
    } else {
        // pixel-major temporal store: [b][p][t][c]
        size_t coff = (size_t)(bz / CT) * ((size_t)CHW * TTC) + (size_t)(bz % CT) * CC;
        #pragma unroll
        for (int i = 0; i < 4; i++) {
            int m = m0 + ty * 4 + i;
            float bv = bias ? bias[m] : 0.f;
            #pragma unroll
            for (int j = 0; j < 4; j++) {
                int n = n0 + tx * 4 + j;
                Cm[coff + (size_t)n * TTC + m] = acc[i][j] * alpha + bv;
            }
        }
    }
}

// ---------------- row softmax over last axis (rows of 1024) -----------------
__global__ __launch_bounds__(256) void softmax_kernel(float* __restrict__ att)
{
    size_t row = (size_t)blockIdx.x * CHW;
    __shared__ float buf[CHW];
    __shared__ float red[8];
    int tid = threadIdx.x, lane = tid & 31, wid = tid >> 5;

    float mx = -3.4e38f;
    #pragma unroll
    for (int r = 0; r < CHW / 256; r++) {
        int i = tid + r * 256;
        float v = att[row + i];
        buf[i] = v;
        mx = fmaxf(mx, v);
    }
    mx = warpMax(mx);
    if (lane == 0) red[wid] = mx;
    __syncthreads();
    if (tid == 0) {
        float m = red[0];
        #pragma unroll
        for (int w = 1; w < 8; w++) m = fmaxf(m, red[w]);
        red[0] = m;
    }
    __syncthreads();
    mx = red[0];
    __syncthreads();

    float s = 0.f;
    #pragma unroll
    for (int r = 0; r < CHW / 256; r++) {
        int i = tid + r * 256;
        float e = __expf(buf[i] - mx);
        buf[i] = e;
        s += e;
    }
    s = warpSum(s);
    if (lane == 0) red[wid] = s;
    __syncthreads();
    if (tid == 0) {
        float S = 0.f;
        #pragma unroll
        for (int w = 0; w < 8; w++) S += red[w];
        red[0] = S;
    }
    __syncthreads();
    float inv = 1.f / red[0];
    #pragma unroll
    for (int r = 0; r < CHW / 256; r++) {
        int i = tid + r * 256;
        att[row + i] = buf[i] * inv;
    }
}

// ---------------- temporal attention: one block per pixel -------------------
// q/k/v/o are pixel-major: [b][p][t][c], base = (b*HW+p)*T*C, contiguous.
__global__ __launch_bounds__(256) void temporal_attn_kernel(
    const float* __restrict__ q, const float* __restrict__ k,
    const float* __restrict__ v, float* __restrict__ o)
{
    size_t base = (size_t)blockIdx.x * TTC;
    int tid = threadIdx.x, lane = tid & 31;

    __shared__ float sacc[CT * CT];
    __shared__ float satt[CT][CT];
    if (tid < CT * CT) sacc[tid] = 0.f;

    float qr[2][CT], kr[2][CT], vr[2][CT];
    float acc[CT][CT] = {};

    #pragma unroll
    for (int r = 0; r < 2; r++) {
        int c = tid + r * 256;
        #pragma unroll
        for (int t = 0; t < CT; t++) {
            qr[r][t] = q[base + t * CC + c];
            kr[r][t] = k[base + t * CC + c];
            vr[r][t] = v[base + t * CC + c];
        }
        #pragma unroll
        for (int t = 0; t < CT; t++)
            #pragma unroll
            for (int s = 0; s < CT; s++)
                acc[t][s] = fmaf(qr[r][t], kr[r][s], acc[t][s]);
    }
    __syncthreads();   // sacc zero-init visible

    #pragma unroll
    for (int t = 0; t < CT; t++)
        #pragma unroll
        for (int s = 0; s < CT; s++) {
            float p = warpSum(acc[t][s]);
            if (lane == 0) atomicAdd(&sacc[t * CT + s], p);
        }
    __syncthreads();

    if (tid < CT) {
        float mx = -3.4e38f;
        #pragma unroll
        for (int s = 0; s < CT; s++) mx = fmaxf(mx, sacc[tid * CT + s] * SCALE);
        float sum = 0.f;
        #pragma unroll
        for (int s = 0; s < CT; s++) {
            float e = __expf(sacc[tid * CT + s] * SCALE - mx);
            satt[tid][s] = e;
            sum += e;
        }
        float inv = 1.f / sum;
        #pragma unroll
        for (int s = 0; s < CT; s++) satt[tid][s] *= inv;
    }
    __syncthreads();

    #pragma unroll
    for (int r = 0; r < 2; r++) {
        int c = tid + r * 256;
        #pragma unroll
        for (int t = 0; t < CT; t++) {
            float ov = 0.f;
            #pragma unroll
            for (int s = 0; s < CT; s++) ov = fmaf(satt[t][s], vr[r][s], ov);
            o[base + t * CC + c] = ov;
        }
    }
}

// ---------------- launch ----------------------------------------------------
extern "C" void kernel_launch(void* const* d_in, const int* in_sizes, int n_in,
                              void* d_out, int out_size)
{
    const float* x     = (const float*)d_in[0];
    const float* wq    = (const float*)d_in[1];
    const float* bq    = (const float*)d_in[2];
    const float* wk    = (const float*)d_in[3];
    const float* bk    = (const float*)d_in[4];
    const float* wv    = (const float*)d_in[5];
    const float* bv    = (const float*)d_in[6];
    const float* wo    = (const float*)d_in[7];
    const float* bo    = (const float*)d_in[8];
    const float* wqt   = (const float*)d_in[9];
    const float* bqt   = (const float*)d_in[10];
    const float* wkt   = (const float*)d_in[11];
    const float* bkt   = (const float*)d_in[12];
    const float* wvt   = (const float*)d_in[13];
    const float* bvt   = (const float*)d_in[14];
    const float* wot   = (const float*)d_in[15];
    const float* bot   = (const float*)d_in[16];
    const float* gamma_s = (const float*)d_in[17];
    const float* beta_s  = (const float*)d_in[18];
    const float* gamma_t = (const float*)d_in[19];
    const float* beta_t  = (const float*)d_in[20];
    float* out = (float*)d_out;

    float *hn, *q, *k, *v, *att, *hsp, *spatio;
    cudaGetSymbolAddress((void**)&hn,     g_hn);
    cudaGetSymbolAddress((void**)&q,      g_q);
    cudaGetSymbolAddress((void**)&k,      g_k);
    cudaGetSymbolAddress((void**)&v,      g_v);
    cudaGetSymbolAddress((void**)&att,    g_att);
    cudaGetSymbolAddress((void**)&hsp,    g_hsp);
    cudaGetSymbolAddress((void**)&spatio, g_spatio);

    const long SCHW = (long)CC * CHW;         // per-image stride [c][p]
    const long SATT = (long)CHW * CHW;        // per-image attention stride

    dim3 gridConv(CC / BM, CHW / BN, CBT);    // M=512, N=1024
    dim3 gridScores(CHW / BM, CHW / BN, CBT); // M=1024, N=1024
    dim3 thr(256);

    // 1) spatial GroupNorm
    groupnorm_kernel<<<CBT * CG, thr>>>(x, hn, gamma_s, beta_s);

    // 2) q/k/v projections (NN conv GEMM)
    gemm_kernel<<<gridConv, thr>>>(wq, hn, q, bq, nullptr, CHW, CC, CC, CHW,
                                   0, SCHW, SCHW, 0, 1.f, 0, 0, 0, 0);
    gemm_kernel<<<gridConv, thr>>>(wk, hn, k, bk, nullptr, CHW, CC, CC, CHW,
                                   0, SCHW, SCHW, 0, 1.f, 0, 0, 0, 0);
    gemm_kernel<<<gridConv, thr>>>(wv, hn, v, bv, nullptr, CHW, CC, CC, CHW,
                                   0, SCHW, SCHW, 0, 1.f, 0, 0, 0, 0);

    // 3) scores = scale * Q^T K  (TN GEMM)
    gemm_kernel<<<gridScores, thr>>>(q, k, att, nullptr, nullptr, CHW, CC, CHW, CHW,
                                     SCHW, SCHW, SATT, 0, SCALE, 1, 0, 0, 0);

    // 4) softmax over keys
    softmax_kernel<<<CBT * CHW, thr>>>(att);

    // 5) hsp = V * Att^T  (NT GEMM)
    gemm_kernel<<<gridConv, thr>>>(v, att, hsp, nullptr, nullptr, CHW, CHW, CHW, CHW,
                                   SCHW, SATT, SCHW, 0, 1.f, 0, 1, 0, 0);

    // 6) spatio = x + Wo*hsp + bo
    gemm_kernel<<<gridConv, thr>>>(wo, hsp, spatio, bo, x, CHW, CC, CC, CHW,
                                   0, SCHW, SCHW, SCHW, 1.f, 0, 0, 0, 0);

    // 7) temporal GroupNorm
    groupnorm_kernel<<<CBT * CG, thr>>>(spatio, hn, gamma_t, beta_t);

    // 8) temporal q/k/v projections, stored pixel-major [b][p][t][c] (cmode=1)
    gemm_kernel<<<gridConv, thr>>>(wqt, hn, q, bqt, nullptr, CHW, CC, CC, CHW,
                                   0, SCHW, 0, 0, 1.f, 0, 0, 0, 1);
    gemm_kernel<<<gridConv, thr>>>(wkt, hn, k, bkt, nullptr, CHW, CC, CC, CHW,
                                   0, SCHW, 0, 0, 1.f, 0, 0, 0, 1);
    gemm_kernel<<<gridConv, thr>>>(wvt, hn, v, bvt, nullptr, CHW, CC, CC, CHW,
                                   0, SCHW, 0, 0, 1.f, 0, 0, 0, 1);

    // 9) per-pixel temporal attention (htp into hsp, pixel-major)
    temporal_attn_kernel<<<CB * CHW, thr>>>(q, k, v, hsp);

    // 10) out = x + Wot*htp + bot  (B from pixel-major layout: tb=1, bmode=1)
    gemm_kernel<<<gridConv, thr>>>(wot, hsp, out, bot, x, CHW, CC, CC, TTC,
                                   0, 0, SCHW, SCHW, 1.f, 0, 1, 1, 0);
}

// round 4
// speedup vs baseline: 3.0321x; 3.0321x over previous
#include <cuda_runtime.h>
#include <cstdint>
#include <math.h>

// ---------------- problem constants ----------------
#define CB   4
#define CT   5
#define CC   512
#define CHW  1024        // H*W
#define CBT  20          // B*T
#define CG   32
#define CPG  16
#define GEPS 1e-6f
#define TTC  (CT*CC)     // 2560 row stride of pixel-major temporal buffers
#define SCALE 0.04419417382415922f   // 512^-0.5

// ---------------- scratch (device globals) ----------------------------------
static __device__ float g_hn[(size_t)CBT*CC*CHW];
static __device__ float g_q [(size_t)CBT*CC*CHW];
static __device__ float g_k [(size_t)CBT*CC*CHW];
static __device__ float g_v [(size_t)CBT*CC*CHW];
static __device__ float g_att[(size_t)CBT*CHW*CHW];
static __device__ float g_hsp[(size_t)CBT*CC*CHW];
static __device__ float g_spatio[(size_t)CBT*CC*CHW];

// ---------------- small helpers ---------------------------------------------
static __inline__ __device__ float warpSum(float v) {
    #pragma unroll
    for (int o = 16; o > 0; o >>= 1) v += __shfl_xor_sync(0xffffffffu, v, o);
    return v;
}
static __inline__ __device__ float warpMax(float v) {
    #pragma unroll
    for (int o = 16; o > 0; o >>= 1) v = fmaxf(v, __shfl_xor_sync(0xffffffffu, v, o));
    return v;
}
static __device__ __forceinline__ float f2tf(float x) {
    uint32_t u;
    asm("cvt.rna.tf32.f32 %0, %1;" : "=r"(u) : "f"(x));
    return __uint_as_float(u);
}
static __device__ __forceinline__ void mma_tf32(float* d, const uint32_t* a, const uint32_t* b) {
    asm volatile(
        "mma.sync.aligned.m16n8k8.row.col.f32.tf32.tf32.f32 "
        "{%0,%1,%2,%3}, {%4,%5,%6,%7}, {%8,%9}, {%0,%1,%2,%3};"
        : "+f"(d[0]), "+f"(d[1]), "+f"(d[2]), "+f"(d[3])
        : "r"(a[0]), "r"(a[1]), "r"(a[2]), "r"(a[3]), "r"(b[0]), "r"(b[1]));
}

// ---------------- tf32 mma.sync GEMM ----------------------------------------
// C[m,n] = alpha * sum_k Aop[m,k] * Bop[k,n]  (+bias[m]) (+resid)
//   tA=0: A gmem [row=m][k] (ld=lda)     tA=1: A gmem [k][m]
//   tB=0: B gmem [row=n][k] (ld=ldb)     tB=1: B gmem [k][n]
//   bmode=1: B batch offset is pixel-major temporal layout
//   cmode=1: store pixel-major C[n*TTC + m]
#define SPAD 132

__global__ __launch_bounds__(256) void gemm_mma(
    const float* __restrict__ A, const float* __restrict__ B, float* __restrict__ Cm,
    const float* __restrict__ bias, const float* __restrict__ resid,
    int N, int K, int lda, int ldb,
    long sA, long sB, long sC, long sR,
    float alpha, int tA, int tB, int bmode, int cmode)
{
    __shared__ __align__(16) float sAt[32][SPAD];
    __shared__ __align__(16) float sBt[32][SPAD];

    int tid = threadIdx.x, wid = tid >> 5, lane = tid & 31;
    int gq = lane >> 2, tg = lane & 3;
    int m0 = blockIdx.x * 128, n0 = blockIdx.y * 128, bz = blockIdx.z;
    int mw = (wid & 3) * 32, nw = (wid >> 2) * 64;

    size_t aoff = (size_t)bz * sA;
    size_t boff = bmode ? (size_t)(bz / CT) * ((size_t)CHW * TTC) + (size_t)(bz % CT) * CC
                        : (size_t)bz * sB;

    float acc[2][8][4];
    #pragma unroll
    for (int mi = 0; mi < 2; mi++)
        #pragma unroll
        for (int ni = 0; ni < 8; ni++)
            #pragma unroll
            for (int c = 0; c < 4; c++) acc[mi][ni][c] = 0.f;

    float4 ra[4], rb[4];

    auto loadA = [&](int k0) {
        #pragma unroll
        for (int i = 0; i < 4; i++) {
            int idx = tid + i * 256;
            if (!tA) {
                int r = idx >> 3, c4 = idx & 7;
                ra[i] = *(const float4*)(A + aoff + (size_t)(m0 + r) * lda + k0 + c4 * 4);
            } else {
                int kk = idx >> 5, m4 = (idx & 31) << 2;
                ra[i] = *(const float4*)(A + aoff + (size_t)(k0 + kk) * lda + m0 + m4);
            }
        }
    };
    auto loadB = [&](int k0) {
        #pragma unroll
        for (int i = 0; i < 4; i++) {
            int idx = tid + i * 256;
            if (!tB) {
                int r = idx >> 3, c4 = idx & 7;
                rb[i] = *(const float4*)(B + boff + (size_t)(n0 + r) * ldb + k0 + c4 * 4);
            } else {
                int kk = idx >> 5, n4 = (idx & 31) << 2;
                rb[i] = *(const float4*)(B + boff + (size_t)(k0 + kk) * ldb + n0 + n4);
            }
        }
    };
    auto storeA = [&]() {
        #pragma unroll
        for (int i = 0; i < 4; i++) {
            int idx = tid + i * 256;
            if (!tA) {
                int r = idx >> 3, c4 = idx & 7;
                sAt[c4 * 4 + 0][r] = f2tf(ra[i].x);
                sAt[c4 * 4 + 1][r] = f2tf(ra[i].y);
                sAt[c4 * 4 + 2][r] = f2tf(ra[i].z);
                sAt[c4 * 4 + 3][r] = f2tf(ra[i].w);
            } else {
                int kk = idx >> 5, m4 = (idx & 31) << 2;
                float4 t;
                t.x = f2tf(ra[i].x); t.y = f2tf(ra[i].y);
                t.z = f2tf(ra[i].z); t.w = f2tf(ra[i].w);
                *(float4*)&sAt[kk][m4] = t;
            }
        }
    };
    auto storeB = [&]() {
        #pragma unroll
        for (int i = 0; i < 4; i++) {
            int idx = tid + i * 256;
            if (!tB) {
                int r = idx >> 3, c4 = idx & 7;
                sBt[c4 * 4 + 0][r] = f2tf(rb[i].x);
                sBt[c4 * 4 + 1][r] = f2tf(rb[i].y);
                sBt[c4 * 4 + 2][r] = f2tf(rb[i].z);
                sBt[c4 * 4 + 3][r] = f2tf(rb[i].w);
            } else {
                int kk = idx >> 5, n4 = (idx & 31) << 2;
                float4 t;
                t.x = f2tf(rb[i].x); t.y = f2tf(rb[i].y);
                t.z = f2tf(rb[i].z); t.w = f2tf(rb[i].w);
                *(float4*)&sBt[kk][n4] = t;
            }
        }
    };

    int NC = K >> 5;
    loadA(0); loadB(0);
    for (int kc = 0; kc < NC; kc++) {
        storeA(); storeB();
        __syncthreads();
        if (kc + 1 < NC) { loadA((kc + 1) << 5); loadB((kc + 1) << 5); }

        #pragma unroll
        for (int ks = 0; ks < 4; ks++) {
            int kb = ks * 8;
            uint32_t af[2][4];
            #pragma unroll
            for (int mi = 0; mi < 2; mi++) {
                int mr = mw + mi * 16;
                af[mi][0] = __float_as_uint(sAt[kb + tg][mr + gq]);
                af[mi][1] = __float_as_uint(sAt[kb + tg][mr + gq + 8]);
                af[mi][2] = __float_as_uint(sAt[kb + tg + 4][mr + gq]);
                af[mi][3] = __float_as_uint(sAt[kb + tg + 4][mr + gq + 8]);
            }
            uint32_t bf[8][2];
            #pragma unroll
            for (int ni = 0; ni < 8; ni++) {
                bf[ni][0] = __float_as_uint(sBt[kb + tg][nw + ni * 8 + gq]);
                bf[ni][1] = __float_as_uint(sBt[kb + tg + 4][nw + ni * 8 + gq]);
            }
            #pragma unroll
            for (int mi = 0; mi < 2; mi++)
                #pragma unroll
                for (int ni = 0; ni < 8; ni++)
                    mma_tf32(acc[mi][ni], af[mi], bf[ni]);
        }
        __syncthreads();
    }

    // ---- epilogue ----
    if (cmode == 0) {
        size_t coff = (size_t)bz * sC;
        size_t roff = (size_t)bz * sR;
        #pragma unroll
        for (int mi = 0; mi < 2; mi++) {
            #pragma unroll
            for (int half = 0; half < 2; half++) {
                int m = m0 + mw + mi * 16 + gq + half * 8;
                float bv = bias ? bias[m] : 0.f;
                #pragma unroll
                for (int ni = 0; ni < 8; ni++) {
                    int n = n0 + nw + ni * 8 + tg * 2;
                    float v0 = acc[mi][ni][half * 2 + 0] * alpha + bv;
                    float v1 = acc[mi][ni][half * 2 + 1] * alpha + bv;
                    if (resid) {
                        v0 += resid[roff + (size_t)m * N + n];
                        v1 += resid[roff + (size_t)m * N + n + 1];
                    }
                    *(float2*)(Cm + coff + (size_t)m * N + n) = make_float2(v0, v1);
                }
            }
        }
    } else {
        size_t coff = (size_t)(bz / CT) * ((size_t)CHW * TTC) + (size_t)(bz % CT) * CC;
        #pragma unroll
        for (int mi = 0; mi < 2; mi++) {
            #pragma unroll
            for (int half = 0; half < 2; half++) {
                int m = m0 + mw + mi * 16 + gq + half * 8;
                float bv = bias ? bias[m] : 0.f;
                #pragma unroll
                for (int ni = 0; ni < 8; ni++) {
                    int n = n0 + nw + ni * 8 + tg * 2;
                    Cm[coff + (size_t)n * TTC + m]       = acc[mi][ni][half * 2 + 0] * alpha + bv;
                    Cm[coff + (size_t)(n + 1) * TTC + m] = acc[mi][ni][half * 2 + 1] * alpha + bv;
                }
            }
        }
    }
}

// ---------------- GroupNorm --------------------------------------------------
__global__ __launch_bounds__(256) void groupnorm_kernel(
    const float* __restrict__ x, float* __restrict__ out,
    const float* __restrict__ gamma, const float* __restrict__ beta)
{
    const int GSZ = CPG * CHW;
    int n = blockIdx.x / CG, g = blockIdx.x % CG;
    size_t base = (size_t)n * CC * CHW + (size_t)g * GSZ;
    int tid = threadIdx.x, lane = tid & 31, wid = tid >> 5;

    float s = 0.f, s2 = 0.f;
    for (int i = tid; i < GSZ; i += 256) {
        float v = x[base + i];
        s += v; s2 += v * v;
    }
    __shared__ float rs[8], rs2[8];
    s = warpSum(s); s2 = warpSum(s2);
    if (lane == 0) { rs[wid] = s; rs2[wid] = s2; }
    __syncthreads();
    if (tid == 0) {
        float S = 0.f, S2 = 0.f;
        #pragma unroll
        for (int w = 0; w < 8; w++) { S += rs[w]; S2 += rs2[w]; }
        rs[0] = S; rs2[0] = S2;
    }
    __syncthreads();
    float mu = rs[0] / (float)GSZ;
    float var = rs2[0] / (float)GSZ - mu * mu;
    float rstd = rsqrtf(var + GEPS);

    for (int i = tid; i < GSZ; i += 256) {
        int c = g * CPG + (i >> 10);
        out[base + i] = (x[base + i] - mu) * rstd * gamma[c] + beta[c];
    }
}

// ---------------- softmax over rows of 1024 ---------------------------------
__global__ __launch_bounds__(256) void softmax_kernel(float* __restrict__ att)
{
    size_t row = (size_t)blockIdx.x * CHW;
    __shared__ float buf[CHW];
    __shared__ float red[8];
    int tid = threadIdx.x, lane = tid & 31, wid = tid >> 5;

    float mx = -3.4e38f;
    #pragma unroll
    for (int r = 0; r < CHW / 256; r++) {
        int i = tid + r * 256;
        float v = att[row + i];
        buf[i] = v;
        mx = fmaxf(mx, v);
    }
    mx = warpMax(mx);
    if (lane == 0) red[wid] = mx;
    __syncthreads();
    if (tid == 0) {
        float m = red[0];
        #pragma unroll
        for (int w = 1; w < 8; w++) m = fmaxf(m, red[w]);
        red[0] = m;
    }
    __syncthreads();
    mx = red[0];
    __syncthreads();

    float s = 0.f;
    #pragma unroll
    for (int r = 0; r < CHW / 256; r++) {
        int i = tid + r * 256;
        float e = __expf(buf[i] - mx);
        buf[i] = e;
        s += e;
    }
    s = warpSum(s);
    if (lane == 0) red[wid] = s;
    __syncthreads();
    if (tid == 0) {
        float S = 0.f;
        #pragma unroll
        for (int w = 0; w < 8; w++) S += red[w];
        red[0] = S;
    }
    __syncthreads();
    float inv = 1.f / red[0];
    #pragma unroll
    for (int r = 0; r < CHW / 256; r++) {
        int i = tid + r * 256;
        att[row + i] = buf[i] * inv;
    }
}

// ---------------- temporal attention ----------------------------------------
__global__ __launch_bounds__(256) void temporal_attn_kernel(
    const float* __restrict__ q, const float* __restrict__ k,
    const float* __restrict__ v, float* __restrict__ o)
{
    size_t base = (size_t)blockIdx.x * TTC;
    int tid = threadIdx.x, lane = tid & 31;

    __shared__ float sacc[CT * CT];
    __shared__ float satt[CT][CT];
    if (tid < CT * CT) sacc[tid] = 0.f;

    float qr[2][CT], kr[2][CT], vr[2][CT];
    float acc[CT][CT] = {};

    #pragma unroll
    for (int r = 0; r < 2; r++) {
        int c = tid + r * 256;
        #pragma unroll
        for (int t = 0; t < CT; t++) {
            qr[r][t] = q[base + t * CC + c];
            kr[r][t] = k[base + t * CC + c];
            vr[r][t] = v[base + t * CC + c];
        }
        #pragma unroll
        for (int t = 0; t < CT; t++)
            #pragma unroll
            for (int s = 0; s < CT; s++)
                acc[t][s] = fmaf(qr[r][t], kr[r][s], acc[t][s]);
    }
    __syncthreads();

    #pragma unroll
    for (int t = 0; t < CT; t++)
        #pragma unroll
        for (int s = 0; s < CT; s++) {
            float p = warpSum(acc[t][s]);
            if (lane == 0) atomicAdd(&sacc[t * CT + s], p);
        }
    __syncthreads();

    if (tid < CT) {
        float mx = -3.4e38f;
        #pragma unroll
        for (int s = 0; s < CT; s++) mx = fmaxf(mx, sacc[tid * CT + s] * SCALE);
        float sum = 0.f;
        #pragma unroll
        for (int s = 0; s < CT; s++) {
            float e = __expf(sacc[tid * CT + s] * SCALE - mx);
            satt[tid][s] = e;
            sum += e;
        }
        float inv = 1.f / sum;
        #pragma unroll
        for (int s = 0; s < CT; s++) satt[tid][s] *= inv;
    }
    __syncthreads();

    #pragma unroll
    for (int r = 0; r < 2; r++) {
        int c = tid + r * 256;
        #pragma unroll
        for (int t = 0; t < CT; t++) {
            float ov = 0.f;
            #pragma unroll
            for (int s = 0; s < CT; s++) ov = fmaf(satt[t][s], vr[r][s], ov);
            o[base + t * CC + c] = ov;
        }
    }
}

// ---------------- launch ----------------------------------------------------
extern "C" void kernel_launch(void* const* d_in, const int* in_sizes, int n_in,
                              void* d_out, int out_size)
{
    const float* x     = (const float*)d_in[0];
    const float* wq    = (const float*)d_in[1];
    const float* bq    = (const float*)d_in[2];
    const float* wk    = (const float*)d_in[3];
    const float* bk    = (const float*)d_in[4];
    const float* wv    = (const float*)d_in[5];
    const float* bv    = (const float*)d_in[6];
    const float* wo    = (const float*)d_in[7];
    const float* bo    = (const float*)d_in[8];
    const float* wqt   = (const float*)d_in[9];
    const float* bqt   = (const float*)d_in[10];
    const float* wkt   = (const float*)d_in[11];
    const float* bkt   = (const float*)d_in[12];
    const float* wvt   = (const float*)d_in[13];
    const float* bvt   = (const float*)d_in[14];
    const float* wot   = (const float*)d_in[15];
    const float* bot   = (const float*)d_in[16];
    const float* gamma_s = (const float*)d_in[17];
    const float* beta_s  = (const float*)d_in[18];
    const float* gamma_t = (const float*)d_in[19];
    const float* beta_t  = (const float*)d_in[20];
    float* out = (float*)d_out;

    float *hn, *q, *k, *v, *att, *hsp, *spatio;
    cudaGetSymbolAddress((void**)&hn,     g_hn);
    cudaGetSymbolAddress((void**)&q,      g_q);
    cudaGetSymbolAddress((void**)&k,      g_k);
    cudaGetSymbolAddress((void**)&v,      g_v);
    cudaGetSymbolAddress((void**)&att,    g_att);
    cudaGetSymbolAddress((void**)&hsp,    g_hsp);
    cudaGetSymbolAddress((void**)&spatio, g_spatio);

    const long SCHW = (long)CC * CHW;
    const long SATT = (long)CHW * CHW;

    dim3 gridConv(CC / 128, CHW / 128, CBT);     // (4, 8, 20)
    dim3 gridScores(CHW / 128, CHW / 128, CBT);  // (8, 8, 20)
    dim3 thr(256);

    // 1) spatial GroupNorm
    groupnorm_kernel<<<CBT * CG, thr>>>(x, hn, gamma_s, beta_s);

    // 2) q/k/v projections: A=W [m][k], B=hn [k][n]
    gemm_mma<<<gridConv, thr>>>(wq, hn, q, bq, nullptr, CHW, CC, CC, CHW,
                                0, SCHW, SCHW, 0, 1.f, 0, 1, 0, 0);
    gemm_mma<<<gridConv, thr>>>(wk, hn, k, bk, nullptr, CHW, CC, CC, CHW,
                                0, SCHW, SCHW, 0, 1.f, 0, 1, 0, 0);
    gemm_mma<<<gridConv, thr>>>(wv, hn, v, bv, nullptr, CHW, CC, CC, CHW,
                                0, SCHW, SCHW, 0, 1.f, 0, 1, 0, 0);

    // 3) scores = scale * Q^T K : A=q [k][m], B=k [k][n]
    gemm_mma<<<gridScores, thr>>>(q, k, att, nullptr, nullptr, CHW, CC, CHW, CHW,
                                  SCHW, SCHW, SATT, 0, SCALE, 1, 1, 0, 0);

    // 4) softmax over keys
    softmax_kernel<<<CBT * CHW, thr>>>(att);

    // 5) hsp = V * Att^T : A=v [m][k], B=att [n][k]
    gemm_mma<<<gridConv, thr>>>(v, att, hsp, nullptr, nullptr, CHW, CHW, CHW, CHW,
                                SCHW, SATT, SCHW, 0, 1.f, 0, 0, 0, 0);

    // 6) spatio = x + Wo*hsp + bo
    gemm_mma<<<gridConv, thr>>>(wo, hsp, spatio, bo, x, CHW, CC, CC, CHW,
                                0, SCHW, SCHW, SCHW, 1.f, 0, 1, 0, 0);

    // 7) temporal GroupNorm
    groupnorm_kernel<<<CBT * CG, thr>>>(spatio, hn, gamma_t, beta_t);

    // 8) temporal q/k/v projections, store pixel-major [b][p][t][c]
    gemm_mma<<<gridConv, thr>>>(wqt, hn, q, bqt, nullptr, CHW, CC, CC, CHW,
                                0, SCHW, 0, 0, 1.f, 0, 1, 0, 1);
    gemm_mma<<<gridConv, thr>>>(wkt, hn, k, bkt, nullptr, CHW, CC, CC, CHW,
                                0, SCHW, 0, 0, 1.f, 0, 1, 0, 1);
    gemm_mma<<<gridConv, thr>>>(wvt, hn, v, bvt, nullptr, CHW, CC, CC, CHW,
                                0, SCHW, 0, 0, 1.f, 0, 1, 0, 1);

    // 9) per-pixel temporal attention (htp into hsp, pixel-major)
    temporal_attn_kernel<<<CB * CHW, thr>>>(q, k, v, hsp);

    // 10) out = x + Wot*htp + bot : B=[n][k] rows via pixel-major (ldb=TTC)
    gemm_mma<<<gridConv, thr>>>(wot, hsp, out, bot, x, CHW, CC, CC, TTC,
                                0, 0, SCHW, SCHW, 1.f, 0, 0, 1, 0);
}

// round 5
// speedup vs baseline: 4.4917x; 1.4814x over previous
#include <cuda_runtime.h>
#include <cstdint>
#include <math.h>

// ---------------- problem constants ----------------
#define CB   4
#define CT   5
#define CC   512
#define CHW  1024        // H*W
#define CBT  20          // B*T
#define CG   32
#define CPG  16
#define GEPS 1e-6f
#define TTC  (CT*CC)     // 2560 row stride of pixel-major temporal buffers
#define SCALE 0.04419417382415922f   // 512^-0.5

// smem tile geometry (floats)
#define AS0  36          // [m][k] row stride (32 + 4 pad)
#define AS1  132         // [k][m] row stride (128 + 4 pad)
#define TILE_F 4608      // max floats per operand tile (128*36)
#define STG_F  (2*TILE_F)   // one stage: A + B
#define STG_B  (STG_F*4)    // bytes
#define SMEM_TOTAL (2*STG_B) // 73728 bytes

// ---------------- scratch (device globals) ----------------------------------
static __device__ float g_hn[(size_t)CBT*CC*CHW];
static __device__ float g_q [(size_t)CBT*CC*CHW];
static __device__ float g_k [(size_t)CBT*CC*CHW];
static __device__ float g_v [(size_t)CBT*CC*CHW];
static __device__ float g_att[(size_t)CBT*CHW*CHW];
static __device__ float g_hsp[(size_t)CBT*CC*CHW];
static __device__ float g_spatio[(size_t)CBT*CC*CHW];

// ---------------- small helpers ---------------------------------------------
static __inline__ __device__ float warpSum(float v) {
    #pragma unroll
    for (int o = 16; o > 0; o >>= 1) v += __shfl_xor_sync(0xffffffffu, v, o);
    return v;
}
static __inline__ __device__ float warpMax(float v) {
    #pragma unroll
    for (int o = 16; o > 0; o >>= 1) v = fmaxf(v, __shfl_xor_sync(0xffffffffu, v, o));
    return v;
}
static __device__ __forceinline__ void mma_tf32(float* d, const uint32_t* a, const uint32_t* b) {
    asm volatile(
        "mma.sync.aligned.m16n8k8.row.col.f32.tf32.tf32.f32 "
        "{%0,%1,%2,%3}, {%4,%5,%6,%7}, {%8,%9}, {%0,%1,%2,%3};"
        : "+f"(d[0]), "+f"(d[1]), "+f"(d[2]), "+f"(d[3])
        : "r"(a[0]), "r"(a[1]), "r"(a[2]), "r"(a[3]), "r"(b[0]), "r"(b[1]));
}
static __device__ __forceinline__ void cp16(uint32_t dst, const float* src) {
    asm volatile("cp.async.cg.shared.global [%0], [%1], 16;" :: "r"(dst), "l"(src));
}
static __device__ __forceinline__ void cp_commit() {
    asm volatile("cp.async.commit_group;" ::: "memory");
}
template<int N> static __device__ __forceinline__ void cp_wait() {
    asm volatile("cp.async.wait_group %0;" :: "n"(N) : "memory");
}

// ---------------- tf32 mma.sync GEMM, cp.async double-buffered ---------------
// C[m,n] = alpha * sum_k Aop[m,k] * Bop[k,n]  (+bias[m]) (+resid)
//   tA=0: A gmem [m][k] (ld=lda)   tA=1: A gmem [k][m]
//   tB=0: B gmem [n][k] (ld=ldb)   tB=1: B gmem [k][n]
//   bmode=1: B batch offset is pixel-major temporal layout
//   cmode=1: store pixel-major C[n*TTC + m]
__global__ __launch_bounds__(256, 2) void gemm_mma(
    const float* __restrict__ A, const float* __restrict__ B, float* __restrict__ Cm,
    const float* __restrict__ bias, const float* __restrict__ resid,
    int N, int K, int lda, int ldb,
    long sA, long sB, long sC, long sR,
    float alpha, int tA, int tB, int bmode, int cmode)
{
    extern __shared__ float smem[];
    uint32_t sbase = (uint32_t)__cvta_generic_to_shared(smem);

    int tid = threadIdx.x, wid = tid >> 5, lane = tid & 31;
    int gq = lane >> 2, tg = lane & 3;
    int m0 = blockIdx.x * 128, n0 = blockIdx.y * 128, bz = blockIdx.z;
    int mw = (wid & 3) * 32, nw = (wid >> 2) * 64;

    size_t aoff = (size_t)bz * sA;
    size_t boff = bmode ? (size_t)(bz / CT) * ((size_t)CHW * TTC) + (size_t)(bz % CT) * CC
                        : (size_t)bz * sB;

    float acc[2][8][4];
    #pragma unroll
    for (int mi = 0; mi < 2; mi++)
        #pragma unroll
        for (int ni = 0; ni < 8; ni++)
            #pragma unroll
            for (int c = 0; c < 4; c++) acc[mi][ni][c] = 0.f;

    auto issue = [&](int kc, int buf) {
        int k0 = kc << 5;
        uint32_t sa = sbase + buf * STG_B;
        uint32_t sb = sa + TILE_F * 4;
        #pragma unroll
        for (int i = 0; i < 4; i++) {
            int c = tid + i * 256;
            if (!tA) {
                int r = c >> 3, q16 = (c & 7) * 4;
                cp16(sa + (uint32_t)(r * AS0 + q16) * 4,
                     A + aoff + (size_t)(m0 + r) * lda + k0 + q16);
            } else {
                int r = c >> 5, off = (c & 31) * 4;
                cp16(sa + (uint32_t)(r * AS1 + off) * 4,
                     A + aoff + (size_t)(k0 + r) * lda + m0 + off);
            }
        }
        #pragma unroll
        for (int i = 0; i < 4; i++) {
            int c = tid + i * 256;
            if (!tB) {
                int r = c >> 3, q16 = (c & 7) * 4;
                cp16(sb + (uint32_t)(r * AS0 + q16) * 4,
                     B + boff + (size_t)(n0 + r) * ldb + k0 + q16);
            } else {
                int r = c >> 5, off = (c & 31) * 4;
                cp16(sb + (uint32_t)(r * AS1 + off) * 4,
                     B + boff + (size_t)(k0 + r) * ldb + n0 + off);
            }
        }
        cp_commit();
    };

    int NC = K >> 5;
    issue(0, 0);
    issue(1, 1);

    for (int kc = 0; kc < NC; kc++) {
        if (kc == NC - 1) cp_wait<0>(); else cp_wait<1>();
        __syncthreads();

        const float* sA_ = smem + (kc & 1) * STG_F;
        const float* sB_ = sA_ + TILE_F;

        #pragma unroll
        for (int ks = 0; ks < 4; ks++) {
            int kb = ks * 8;
            uint32_t af[2][4];
            #pragma unroll
            for (int mi = 0; mi < 2; mi++) {
                int mr = mw + mi * 16 + gq;
                if (!tA) {
                    af[mi][0] = __float_as_uint(sA_[(mr)     * AS0 + kb + tg]);
                    af[mi][1] = __float_as_uint(sA_[(mr + 8) * AS0 + kb + tg]);
                    af[mi][2] = __float_as_uint(sA_[(mr)     * AS0 + kb + tg + 4]);
                    af[mi][3] = __float_as_uint(sA_[(mr + 8) * AS0 + kb + tg + 4]);
                } else {
                    af[mi][0] = __float_as_uint(sA_[(kb + tg)     * AS1 + mr]);
                    af[mi][1] = __float_as_uint(sA_[(kb + tg)     * AS1 + mr + 8]);
                    af[mi][2] = __float_as_uint(sA_[(kb + tg + 4) * AS1 + mr]);
                    af[mi][3] = __float_as_uint(sA_[(kb + tg + 4) * AS1 + mr + 8]);
                }
            }
            uint32_t bf[8][2];
            #pragma unroll
            for (int ni = 0; ni < 8; ni++) {
                int nn = nw + ni * 8 + gq;
                if (!tB) {
                    bf[ni][0] = __float_as_uint(sB_[nn * AS0 + kb + tg]);
                    bf[ni][1] = __float_as_uint(sB_[nn * AS0 + kb + tg + 4]);
                } else {
                    bf[ni][0] = __float_as_uint(sB_[(kb + tg)     * AS1 + nn]);
                    bf[ni][1] = __float_as_uint(sB_[(kb + tg + 4) * AS1 + nn]);
                }
            }
            #pragma unroll
            for (int mi = 0; mi < 2; mi++)
                #pragma unroll
                for (int ni = 0; ni < 8; ni++)
                    mma_tf32(acc[mi][ni], af[mi], bf[ni]);
        }
        __syncthreads();
        if (kc + 2 < NC) issue(kc + 2, kc & 1);
    }

    // ---- epilogue ----
    if (cmode == 0) {
        size_t coff = (size_t)bz * sC;
        size_t roff = (size_t)bz * sR;
        #pragma unroll
        for (int mi = 0; mi < 2; mi++) {
            #pragma unroll
            for (int half = 0; half < 2; half++) {
                int m = m0 + mw + mi * 16 + gq + half * 8;
                float bv = bias ? bias[m] : 0.f;
                #pragma unroll
                for (int ni = 0; ni < 8; ni++) {
                    int n = n0 + nw + ni * 8 + tg * 2;
                    float v0 = acc[mi][ni][half * 2 + 0] * alpha + bv;
                    float v1 = acc[mi][ni][half * 2 + 1] * alpha + bv;
                    if (resid) {
                        v0 += resid[roff + (size_t)m * N + n];
                        v1 += resid[roff + (size_t)m * N + n + 1];
                    }
                    *(float2*)(Cm + coff + (size_t)m * N + n) = make_float2(v0, v1);
                }
            }
        }
    } else {
        size_t coff = (size_t)(bz / CT) * ((size_t)CHW * TTC) + (size_t)(bz % CT) * CC;
        #pragma unroll
        for (int mi = 0; mi < 2; mi++) {
            #pragma unroll
            for (int half = 0; half < 2; half++) {
                int m = m0 + mw + mi * 16 + gq + half * 8;
                float bv = bias ? bias[m] : 0.f;
                #pragma unroll
                for (int ni = 0; ni < 8; ni++) {
                    int n = n0 + nw + ni * 8 + tg * 2;
                    Cm[coff + (size_t)n * TTC + m]       = acc[mi][ni][half * 2 + 0] * alpha + bv;
                    Cm[coff + (size_t)(n + 1) * TTC + m] = acc[mi][ni][half * 2 + 1] * alpha + bv;
                }
            }
        }
    }
}

// ---------------- GroupNorm --------------------------------------------------
__global__ __launch_bounds__(256) void groupnorm_kernel(
    const float* __restrict__ x, float* __restrict__ out,
    const float* __restrict__ gamma, const float* __restrict__ beta)
{
    const int GSZ = CPG * CHW;
    int n = blockIdx.x / CG, g = blockIdx.x % CG;
    size_t base = (size_t)n * CC * CHW + (size_t)g * GSZ;
    int tid = threadIdx.x, lane = tid & 31, wid = tid >> 5;

    float s = 0.f, s2 = 0.f;
    for (int i = tid; i < GSZ; i += 256) {
        float v = x[base + i];
        s += v; s2 += v * v;
    }
    __shared__ float rs[8], rs2[8];
    s = warpSum(s); s2 = warpSum(s2);
    if (lane == 0) { rs[wid] = s; rs2[wid] = s2; }
    __syncthreads();
    if (tid == 0) {
        float S = 0.f, S2 = 0.f;
        #pragma unroll
        for (int w = 0; w < 8; w++) { S += rs[w]; S2 += rs2[w]; }
        rs[0] = S; rs2[0] = S2;
    }
    __syncthreads();
    float mu = rs[0] / (float)GSZ;
    float var = rs2[0] / (float)GSZ - mu * mu;
    float rstd = rsqrtf(var + GEPS);

    for (int i = tid; i < GSZ; i += 256) {
        int c = g * CPG + (i >> 10);
        out[base + i] = (x[base + i] - mu) * rstd * gamma[c] + beta[c];
    }
}

// ---------------- softmax over rows of 1024 ---------------------------------
__global__ __launch_bounds__(256) void softmax_kernel(float* __restrict__ att)
{
    size_t row = (size_t)blockIdx.x * CHW;
    __shared__ float buf[CHW];
    __shared__ float red[8];
    int tid = threadIdx.x, lane = tid & 31, wid = tid >> 5;

    float mx = -3.4e38f;
    #pragma unroll
    for (int r = 0; r < CHW / 256; r++) {
        int i = tid + r * 256;
        float v = att[row + i];
        buf[i] = v;
        mx = fmaxf(mx, v);
    }
    mx = warpMax(mx);
    if (lane == 0) red[wid] = mx;
    __syncthreads();
    if (tid == 0) {
        float m = red[0];
        #pragma unroll
        for (int w = 1; w < 8; w++) m = fmaxf(m, red[w]);
        red[0] = m;
    }
    __syncthreads();
    mx = red[0];
    __syncthreads();

    float s = 0.f;
    #pragma unroll
    for (int r = 0; r < CHW / 256; r++) {
        int i = tid + r * 256;
        float e = __expf(buf[i] - mx);
        buf[i] = e;
        s += e;
    }
    s = warpSum(s);
    if (lane == 0) red[wid] = s;
    __syncthreads();
    if (tid == 0) {
        float S = 0.f;
        #pragma unroll
        for (int w = 0; w < 8; w++) S += red[w];
        red[0] = S;
    }
    __syncthreads();
    float inv = 1.f / red[0];
    #pragma unroll
    for (int r = 0; r < CHW / 256; r++) {
        int i = tid + r * 256;
        att[row + i] = buf[i] * inv;
    }
}

// ---------------- temporal attention ----------------------------------------
__global__ __launch_bounds__(256) void temporal_attn_kernel(
    const float* __restrict__ q, const float* __restrict__ k,
    const float* __restrict__ v, float* __restrict__ o)
{
    size_t base = (size_t)blockIdx.x * TTC;
    int tid = threadIdx.x, lane = tid & 31;

    __shared__ float sacc[CT * CT];
    __shared__ float satt[CT][CT];
    if (tid < CT * CT) sacc[tid] = 0.f;

    float qr[2][CT], kr[2][CT], vr[2][CT];
    float acc[CT][CT] = {};

    #pragma unroll
    for (int r = 0; r < 2; r++) {
        int c = tid + r * 256;
        #pragma unroll
        for (int t = 0; t < CT; t++) {
            qr[r][t] = q[base + t * CC + c];
            kr[r][t] = k[base + t * CC + c];
            vr[r][t] = v[base + t * CC + c];
        }
        #pragma unroll
        for (int t = 0; t < CT; t++)
            #pragma unroll
            for (int s = 0; s < CT; s++)
                acc[t][s] = fmaf(qr[r][t], kr[r][s], acc[t][s]);
    }
    __syncthreads();

    #pragma unroll
    for (int t = 0; t < CT; t++)
        #pragma unroll
        for (int s = 0; s < CT; s++) {
            float p = warpSum(acc[t][s]);
            if (lane == 0) atomicAdd(&sacc[t * CT + s], p);
        }
    __syncthreads();

    if (tid < CT) {
        float mx = -3.4e38f;
        #pragma unroll
        for (int s = 0; s < CT; s++) mx = fmaxf(mx, sacc[tid * CT + s] * SCALE);
        float sum = 0.f;
        #pragma unroll
        for (int s = 0; s < CT; s++) {
            float e = __expf(sacc[tid * CT + s] * SCALE - mx);
            satt[tid][s] = e;
            sum += e;
        }
        float inv = 1.f / sum;
        #pragma unroll
        for (int s = 0; s < CT; s++) satt[tid][s] *= inv;
    }
    __syncthreads();

    #pragma unroll
    for (int r = 0; r < 2; r++) {
        int c = tid + r * 256;
        #pragma unroll
        for (int t = 0; t < CT; t++) {
            float ov = 0.f;
            #pragma unroll
            for (int s = 0; s < CT; s++) ov = fmaf(satt[t][s], vr[r][s], ov);
            o[base + t * CC + c] = ov;
        }
    }
}

// ---------------- launch ----------------------------------------------------
extern "C" void kernel_launch(void* const* d_in, const int* in_sizes, int n_in,
                              void* d_out, int out_size)
{
    const float* x     = (const float*)d_in[0];
    const float* wq    = (const float*)d_in[1];
    const float* bq    = (const float*)d_in[2];
    const float* wk    = (const float*)d_in[3];
    const float* bk    = (const float*)d_in[4];
    const float* wv    = (const float*)d_in[5];
    const float* bv    = (const float*)d_in[6];
    const float* wo    = (const float*)d_in[7];
    const float* bo    = (const float*)d_in[8];
    const float* wqt   = (const float*)d_in[9];
    const float* bqt   = (const float*)d_in[10];
    const float* wkt   = (const float*)d_in[11];
    const float* bkt   = (const float*)d_in[12];
    const float* wvt   = (const float*)d_in[13];
    const float* bvt   = (const float*)d_in[14];
    const float* wot   = (const float*)d_in[15];
    const float* bot   = (const float*)d_in[16];
    const float* gamma_s = (const float*)d_in[17];
    const float* beta_s  = (const float*)d_in[18];
    const float* gamma_t = (const float*)d_in[19];
    const float* beta_t  = (const float*)d_in[20];
    float* out = (float*)d_out;

    float *hn, *q, *k, *v, *att, *hsp, *spatio;
    cudaGetSymbolAddress((void**)&hn,     g_hn);
    cudaGetSymbolAddress((void**)&q,      g_q);
    cudaGetSymbolAddress((void**)&k,      g_k);
    cudaGetSymbolAddress((void**)&v,      g_v);
    cudaGetSymbolAddress((void**)&att,    g_att);
    cudaGetSymbolAddress((void**)&hsp,    g_hsp);
    cudaGetSymbolAddress((void**)&spatio, g_spatio);

    cudaFuncSetAttribute(gemm_mma, cudaFuncAttributeMaxDynamicSharedMemorySize, SMEM_TOTAL);

    const long SCHW = (long)CC * CHW;
    const long SATT = (long)CHW * CHW;

    dim3 gridConv(CC / 128, CHW / 128, CBT);     // (4, 8, 20)
    dim3 gridScores(CHW / 128, CHW / 128, CBT);  // (8, 8, 20)
    dim3 thr(256);

    // 1) spatial GroupNorm
    groupnorm_kernel<<<CBT * CG, thr>>>(x, hn, gamma_s, beta_s);

    // 2) q/k/v projections: A=W [m][k], B=hn [k][n]
    gemm_mma<<<gridConv, thr, SMEM_TOTAL>>>(wq, hn, q, bq, nullptr, CHW, CC, CC, CHW,
                                0, SCHW, SCHW, 0, 1.f, 0, 1, 0, 0);
    gemm_mma<<<gridConv, thr, SMEM_TOTAL>>>(wk, hn, k, bk, nullptr, CHW, CC, CC, CHW,
                                0, SCHW, SCHW, 0, 1.f, 0, 1, 0, 0);
    gemm_mma<<<gridConv, thr, SMEM_TOTAL>>>(wv, hn, v, bv, nullptr, CHW, CC, CC, CHW,
                                0, SCHW, SCHW, 0, 1.f, 0, 1, 0, 0);

    // 3) scores = scale * Q^T K : A=q [k][m], B=k [k][n]
    gemm_mma<<<gridScores, thr, SMEM_TOTAL>>>(q, k, att, nullptr, nullptr, CHW, CC, CHW, CHW,
                                  SCHW, SCHW, SATT, 0, SCALE, 1, 1, 0, 0);

    // 4) softmax over keys
    softmax_kernel<<<CBT * CHW, thr>>>(att);

    // 5) hsp = V * Att^T : A=v [m][k], B=att [n][k]
    gemm_mma<<<gridConv, thr, SMEM_TOTAL>>>(v, att, hsp, nullptr, nullptr, CHW, CHW, CHW, CHW,
                                SCHW, SATT, SCHW, 0, 1.f, 0, 0, 0, 0);

    // 6) spatio = x + Wo*hsp + bo
    gemm_mma<<<gridConv, thr, SMEM_TOTAL>>>(wo, hsp, spatio, bo, x, CHW, CC, CC, CHW,
                                0, SCHW, SCHW, SCHW, 1.f, 0, 1, 0, 0);

    // 7) temporal GroupNorm
    groupnorm_kernel<<<CBT * CG, thr>>>(spatio, hn, gamma_t, beta_t);

    // 8) temporal q/k/v projections, store pixel-major [b][p][t][c]
    gemm_mma<<<gridConv, thr, SMEM_TOTAL>>>(wqt, hn, q, bqt, nullptr, CHW, CC, CC, CHW,
                                0, SCHW, 0, 0, 1.f, 0, 1, 0, 1);
    gemm_mma<<<gridConv, thr, SMEM_TOTAL>>>(wkt, hn, k, bkt, nullptr, CHW, CC, CC, CHW,
                                0, SCHW, 0, 0, 1.f, 0, 1, 0, 1);
    gemm_mma<<<gridConv, thr, SMEM_TOTAL>>>(wvt, hn, v, bvt, nullptr, CHW, CC, CC, CHW,
                                0, SCHW, 0, 0, 1.f, 0, 1, 0, 1);

    // 9) per-pixel temporal attention (htp into hsp, pixel-major)
    temporal_attn_kernel<<<CB * CHW, thr>>>(q, k, v, hsp);

    // 10) out = x + Wot*htp + bot : B=[n][k] rows via pixel-major (ldb=TTC)
    gemm_mma<<<gridConv, thr, SMEM_TOTAL>>>(wot, hsp, out, bot, x, CHW, CC, CC, TTC,
                                0, 0, SCHW, SCHW, 1.f, 0, 0, 1, 0);
}

// round 6
// speedup vs baseline: 4.8825x; 1.0870x over previous
#include <cuda_runtime.h>
#include <cstdint>
#include <math.h>

// ---------------- problem constants ----------------
#define CB   4
#define CT   5
#define CC   512
#define CHW  1024        // H*W
#define CBT  20          // B*T
#define CG   32
#define CPG  16
#define GEPS 1e-6f
#define TTC  (CT*CC)     // 2560 row stride of pixel-major temporal buffers
#define SCALE 0.04419417382415922f   // 512^-0.5

// smem tile geometry (floats)
#define AS0  36          // [m][k] row stride (32 + 4 pad)
#define AS1  136         // [k][m] row stride (128 + 8 pad) -> conflict-free 8*tg+gq
#define TILE_F 4608      // max floats per operand tile (128*36 >= 32*136)
#define STG_F  (2*TILE_F)    // one stage: A + B
#define STG_B  (STG_F*4)     // 36864 bytes
#define NSTAGE 3
#define SMEM_TOTAL (NSTAGE*STG_B)  // 110592 bytes

// ---------------- scratch (device globals) ----------------------------------
static __device__ float g_hn[(size_t)CBT*CC*CHW];
static __device__ float g_q [(size_t)CBT*CC*CHW];
static __device__ float g_k [(size_t)CBT*CC*CHW];
static __device__ float g_v [(size_t)CBT*CC*CHW];
static __device__ float g_att[(size_t)CBT*CHW*CHW];
static __device__ float g_hsp[(size_t)CBT*CC*CHW];
static __device__ float g_spatio[(size_t)CBT*CC*CHW];

// ---------------- small helpers ---------------------------------------------
static __inline__ __device__ float warpSum(float v) {
    #pragma unroll
    for (int o = 16; o > 0; o >>= 1) v += __shfl_xor_sync(0xffffffffu, v, o);
    return v;
}
static __inline__ __device__ float warpMax(float v) {
    #pragma unroll
    for (int o = 16; o > 0; o >>= 1) v = fmaxf(v, __shfl_xor_sync(0xffffffffu, v, o));
    return v;
}
static __device__ __forceinline__ void mma_tf32(float* d, const uint32_t* a, const uint32_t* b) {
    asm volatile(
        "mma.sync.aligned.m16n8k8.row.col.f32.tf32.tf32.f32 "
        "{%0,%1,%2,%3}, {%4,%5,%6,%7}, {%8,%9}, {%0,%1,%2,%3};"
        : "+f"(d[0]), "+f"(d[1]), "+f"(d[2]), "+f"(d[3])
        : "r"(a[0]), "r"(a[1]), "r"(a[2]), "r"(a[3]), "r"(b[0]), "r"(b[1]));
}
static __device__ __forceinline__ void cp16(uint32_t dst, const float* src) {
    asm volatile("cp.async.cg.shared.global [%0], [%1], 16;" :: "r"(dst), "l"(src));
}
static __device__ __forceinline__ void cp_commit() {
    asm volatile("cp.async.commit_group;" ::: "memory");
}
template<int N> static __device__ __forceinline__ void cp_wait() {
    asm volatile("cp.async.wait_group %0;" :: "n"(N) : "memory");
}

// ---------------- tf32 mma.sync GEMM, cp.async 3-stage pipeline --------------
// C[m,n] = alpha * sum_k Aop[m,k] * Bop[k,n]  (+bias[m]) (+resid)
//   tA=0: A gmem [m][k] (ld=lda)   tA=1: A gmem [k][m]
//   tB=0: B gmem [n][k] (ld=ldb)   tB=1: B gmem [k][n]
//   bmode=1: B batch offset is pixel-major temporal layout
//   cmode=1: store pixel-major C[n*TTC + m]
__global__ __launch_bounds__(256, 2) void gemm_mma(
    const float* __restrict__ A, const float* __restrict__ B, float* __restrict__ Cm,
    const float* __restrict__ bias, const float* __restrict__ resid,
    int N, int K, int lda, int ldb,
    long sA, long sB, long sC, long sR,
    float alpha, int tA, int tB, int bmode, int cmode)
{
    extern __shared__ float smem[];
    uint32_t sbase = (uint32_t)__cvta_generic_to_shared(smem);

    int tid = threadIdx.x, wid = tid >> 5, lane = tid & 31;
    int gq = lane >> 2, tg = lane & 3;
    int m0 = blockIdx.x * 128, n0 = blockIdx.y * 128, bz = blockIdx.z;
    int mw = (wid & 3) * 32, nw = (wid >> 2) * 64;

    size_t aoff = (size_t)bz * sA;
    size_t boff = bmode ? (size_t)(bz / CT) * ((size_t)CHW * TTC) + (size_t)(bz % CT) * CC
                        : (size_t)bz * sB;

    float acc[2][8][4];
    #pragma unroll
    for (int mi = 0; mi < 2; mi++)
        #pragma unroll
        for (int ni = 0; ni < 8; ni++)
            #pragma unroll
            for (int c = 0; c < 4; c++) acc[mi][ni][c] = 0.f;

    auto issue = [&](int kc, int buf) {
        int k0 = kc << 5;
        uint32_t sa = sbase + buf * STG_B;
        uint32_t sb = sa + TILE_F * 4;
        #pragma unroll
        for (int i = 0; i < 4; i++) {
            int c = tid + i * 256;
            if (!tA) {
                int r = c >> 3, q16 = (c & 7) * 4;
                cp16(sa + (uint32_t)(r * AS0 + q16) * 4,
                     A + aoff + (size_t)(m0 + r) * lda + k0 + q16);
            } else {
                int r = c >> 5, off = (c & 31) * 4;
                cp16(sa + (uint32_t)(r * AS1 + off) * 4,
                     A + aoff + (size_t)(k0 + r) * lda + m0 + off);
            }
        }
        #pragma unroll
        for (int i = 0; i < 4; i++) {
            int c = tid + i * 256;
            if (!tB) {
                int r = c >> 3, q16 = (c & 7) * 4;
                cp16(sb + (uint32_t)(r * AS0 + q16) * 4,
                     B + boff + (size_t)(n0 + r) * ldb + k0 + q16);
            } else {
                int r = c >> 5, off = (c & 31) * 4;
                cp16(sb + (uint32_t)(r * AS1 + off) * 4,
                     B + boff + (size_t)(k0 + r) * ldb + n0 + off);
            }
        }
        cp_commit();
    };

    int NC = K >> 5;
    issue(0, 0);
    issue(1, 1);
    issue(2, 2);

    int buf = 0;
    for (int kc = 0; kc < NC; kc++) {
        if (kc < NC - 2)      cp_wait<2>();
        else if (kc == NC - 2) cp_wait<1>();
        else                   cp_wait<0>();
        __syncthreads();

        const float* sA_ = smem + buf * STG_F;
        const float* sB_ = sA_ + TILE_F;

        #pragma unroll
        for (int ks = 0; ks < 4; ks++) {
            int kb = ks * 8;
            uint32_t af[2][4];
            #pragma unroll
            for (int mi = 0; mi < 2; mi++) {
                int mr = mw + mi * 16 + gq;
                if (!tA) {
                    af[mi][0] = __float_as_uint(sA_[(mr)     * AS0 + kb + tg]);
                    af[mi][1] = __float_as_uint(sA_[(mr + 8) * AS0 + kb + tg]);
                    af[mi][2] = __float_as_uint(sA_[(mr)     * AS0 + kb + tg + 4]);
                    af[mi][3] = __float_as_uint(sA_[(mr + 8) * AS0 + kb + tg + 4]);
                } else {
                    af[mi][0] = __float_as_uint(sA_[(kb + tg)     * AS1 + mr]);
                    af[mi][1] = __float_as_uint(sA_[(kb + tg)     * AS1 + mr + 8]);
                    af[mi][2] = __float_as_uint(sA_[(kb + tg + 4) * AS1 + mr]);
                    af[mi][3] = __float_as_uint(sA_[(kb + tg + 4) * AS1 + mr + 8]);
                }
            }
            uint32_t bf[8][2];
            #pragma unroll
            for (int ni = 0; ni < 8; ni++) {
                int nn = nw + ni * 8 + gq;
                if (!tB) {
                    bf[ni][0] = __float_as_uint(sB_[nn * AS0 + kb + tg]);
                    bf[ni][1] = __float_as_uint(sB_[nn * AS0 + kb + tg + 4]);
                } else {
                    bf[ni][0] = __float_as_uint(sB_[(kb + tg)     * AS1 + nn]);
                    bf[ni][1] = __float_as_uint(sB_[(kb + tg + 4) * AS1 + nn]);
                }
            }
            #pragma unroll
            for (int mi = 0; mi < 2; mi++)
                #pragma unroll
                for (int ni = 0; ni < 8; ni++)
                    mma_tf32(acc[mi][ni], af[mi], bf[ni]);
        }
        __syncthreads();
        if (kc + NSTAGE < NC) issue(kc + NSTAGE, buf);
        buf = (buf == NSTAGE - 1) ? 0 : buf + 1;
    }

    // ---- epilogue ----
    if (cmode == 0) {
        size_t coff = (size_t)bz * sC;
        size_t roff = (size_t)bz * sR;
        #pragma unroll
        for (int mi = 0; mi < 2; mi++) {
            #pragma unroll
            for (int half = 0; half < 2; half++) {
                int m = m0 + mw + mi * 16 + gq + half * 8;
                float bv = bias ? bias[m] : 0.f;
                #pragma unroll
                for (int ni = 0; ni < 8; ni++) {
                    int n = n0 + nw + ni * 8 + tg * 2;
                    float v0 = acc[mi][ni][half * 2 + 0] * alpha + bv;
                    float v1 = acc[mi][ni][half * 2 + 1] * alpha + bv;
                    if (resid) {
                        v0 += resid[roff + (size_t)m * N + n];
                        v1 += resid[roff + (size_t)m * N + n + 1];
                    }
                    *(float2*)(Cm + coff + (size_t)m * N + n) = make_float2(v0, v1);
                }
            }
        }
    } else {
        size_t coff = (size_t)(bz / CT) * ((size_t)CHW * TTC) + (size_t)(bz % CT) * CC;
        #pragma unroll
        for (int mi = 0; mi < 2; mi++) {
            #pragma unroll
            for (int half = 0; half < 2; half++) {
                int m = m0 + mw + mi * 16 + gq + half * 8;
                float bv = bias ? bias[m] : 0.f;
                #pragma unroll
                for (int ni = 0; ni < 8; ni++) {
                    int n = n0 + nw + ni * 8 + tg * 2;
                    Cm[coff + (size_t)n * TTC + m]       = acc[mi][ni][half * 2 + 0] * alpha + bv;
                    Cm[coff + (size_t)(n + 1) * TTC + m] = acc[mi][ni][half * 2 + 1] * alpha + bv;
                }
            }
        }
    }
}

// ---------------- GroupNorm --------------------------------------------------
__global__ __launch_bounds__(256) void groupnorm_kernel(
    const float* __restrict__ x, float* __restrict__ out,
    const float* __restrict__ gamma, const float* __restrict__ beta)
{
    const int GSZ = CPG * CHW;
    int n = blockIdx.x / CG, g = blockIdx.x % CG;
    size_t base = (size_t)n * CC * CHW + (size_t)g * GSZ;
    int tid = threadIdx.x, lane = tid & 31, wid = tid >> 5;

    float s = 0.f, s2 = 0.f;
    for (int i = tid; i < GSZ; i += 256) {
        float v = x[base + i];
        s += v; s2 += v * v;
    }
    __shared__ float rs[8], rs2[8];
    s = warpSum(s); s2 = warpSum(s2);
    if (lane == 0) { rs[wid] = s; rs2[wid] = s2; }
    __syncthreads();
    if (tid == 0) {
        float S = 0.f, S2 = 0.f;
        #pragma unroll
        for (int w = 0; w < 8; w++) { S += rs[w]; S2 += rs2[w]; }
        rs[0] = S; rs2[0] = S2;
    }
    __syncthreads();
    float mu = rs[0] / (float)GSZ;
    float var = rs2[0] / (float)GSZ - mu * mu;
    float rstd = rsqrtf(var + GEPS);

    for (int i = tid; i < GSZ; i += 256) {
        int c = g * CPG + (i >> 10);
        out[base + i] = (x[base + i] - mu) * rstd * gamma[c] + beta[c];
    }
}

// ---------------- softmax over rows of 1024 ---------------------------------
__global__ __launch_bounds__(256) void softmax_kernel(float* __restrict__ att)
{
    size_t row = (size_t)blockIdx.x * CHW;
    __shared__ float buf[CHW];
    __shared__ float red[8];
    int tid = threadIdx.x, lane = tid & 31, wid = tid >> 5;

    float mx = -3.4e38f;
    #pragma unroll
    for (int r = 0; r < CHW / 256; r++) {
        int i = tid + r * 256;
        float v = att[row + i];
        buf[i] = v;
        mx = fmaxf(mx, v);
    }
    mx = warpMax(mx);
    if (lane == 0) red[wid] = mx;
    __syncthreads();
    if (tid == 0) {
        float m = red[0];
        #pragma unroll
        for (int w = 1; w < 8; w++) m = fmaxf(m, red[w]);
        red[0] = m;
    }
    __syncthreads();
    mx = red[0];
    __syncthreads();

    float s = 0.f;
    #pragma unroll
    for (int r = 0; r < CHW / 256; r++) {
        int i = tid + r * 256;
        float e = __expf(buf[i] - mx);
        buf[i] = e;
        s += e;
    }
    s = warpSum(s);
    if (lane == 0) red[wid] = s;
    __syncthreads();
    if (tid == 0) {
        float S = 0.f;
        #pragma unroll
        for (int w = 0; w < 8; w++) S += red[w];
        red[0] = S;
    }
    __syncthreads();
    float inv = 1.f / red[0];
    #pragma unroll
    for (int r = 0; r < CHW / 256; r++) {
        int i = tid + r * 256;
        att[row + i] = buf[i] * inv;
    }
}

// ---------------- temporal attention ----------------------------------------
__global__ __launch_bounds__(256) void temporal_attn_kernel(
    const float* __restrict__ q, const float* __restrict__ k,
    const float* __restrict__ v, float* __restrict__ o)
{
    size_t base = (size_t)blockIdx.x * TTC;
    int tid = threadIdx.x, lane = tid & 31;

    __shared__ float sacc[CT * CT];
    __shared__ float satt[CT][CT];
    if (tid < CT * CT) sacc[tid] = 0.f;

    float qr[2][CT], kr[2][CT], vr[2][CT];
    float acc[CT][CT] = {};

    #pragma unroll
    for (int r = 0; r < 2; r++) {
        int c = tid + r * 256;
        #pragma unroll
        for (int t = 0; t < CT; t++) {
            qr[r][t] = q[base + t * CC + c];
            kr[r][t] = k[base + t * CC + c];
            vr[r][t] = v[base + t * CC + c];
        }
        #pragma unroll
        for (int t = 0; t < CT; t++)
            #pragma unroll
            for (int s = 0; s < CT; s++)
                acc[t][s] = fmaf(qr[r][t], kr[r][s], acc[t][s]);
    }
    __syncthreads();

    #pragma unroll
    for (int t = 0; t < CT; t++)
        #pragma unroll
        for (int s = 0; s < CT; s++) {
            float p = warpSum(acc[t][s]);
            if (lane == 0) atomicAdd(&sacc[t * CT + s], p);
        }
    __syncthreads();

    if (tid < CT) {
        float mx = -3.4e38f;
        #pragma unroll
        for (int s = 0; s < CT; s++) mx = fmaxf(mx, sacc[tid * CT + s] * SCALE);
        float sum = 0.f;
        #pragma unroll
        for (int s = 0; s < CT; s++) {
            float e = __expf(sacc[tid * CT + s] * SCALE - mx);
            satt[tid][s] = e;
            sum += e;
        }
        float inv = 1.f / sum;
        #pragma unroll
        for (int s = 0; s < CT; s++) satt[tid][s] *= inv;
    }
    __syncthreads();

    #pragma unroll
    for (int r = 0; r < 2; r++) {
        int c = tid + r * 256;
        #pragma unroll
        for (int t = 0; t < CT; t++) {
            float ov = 0.f;
            #pragma unroll
            for (int s = 0; s < CT; s++) ov = fmaf(satt[t][s], vr[r][s], ov);
            o[base + t * CC + c] = ov;
        }
    }
}

// ---------------- launch ----------------------------------------------------
extern "C" void kernel_launch(void* const* d_in, const int* in_sizes, int n_in,
                              void* d_out, int out_size)
{
    const float* x     = (const float*)d_in[0];
    const float* wq    = (const float*)d_in[1];
    const float* bq    = (const float*)d_in[2];
    const float* wk    = (const float*)d_in[3];
    const float* bk    = (const float*)d_in[4];
    const float* wv    = (const float*)d_in[5];
    const float* bv    = (const float*)d_in[6];
    const float* wo    = (const float*)d_in[7];
    const float* bo    = (const float*)d_in[8];
    const float* wqt   = (const float*)d_in[9];
    const float* bqt   = (const float*)d_in[10];
    const float* wkt   = (const float*)d_in[11];
    const float* bkt   = (const float*)d_in[12];
    const float* wvt   = (const float*)d_in[13];
    const float* bvt   = (const float*)d_in[14];
    const float* wot   = (const float*)d_in[15];
    const float* bot   = (const float*)d_in[16];
    const float* gamma_s = (const float*)d_in[17];
    const float* beta_s  = (const float*)d_in[18];
    const float* gamma_t = (const float*)d_in[19];
    const float* beta_t  = (const float*)d_in[20];
    float* out = (float*)d_out;

    float *hn, *q, *k, *v, *att, *hsp, *spatio;
    cudaGetSymbolAddress((void**)&hn,     g_hn);
    cudaGetSymbolAddress((void**)&q,      g_q);
    cudaGetSymbolAddress((void**)&k,      g_k);
    cudaGetSymbolAddress((void**)&v,      g_v);
    cudaGetSymbolAddress((void**)&att,    g_att);
    cudaGetSymbolAddress((void**)&hsp,    g_hsp);
    cudaGetSymbolAddress((void**)&spatio, g_spatio);

    cudaFuncSetAttribute(gemm_mma, cudaFuncAttributeMaxDynamicSharedMemorySize, SMEM_TOTAL);

    const long SCHW = (long)CC * CHW;
    const long SATT = (long)CHW * CHW;

    dim3 gridConv(CC / 128, CHW / 128, CBT);     // (4, 8, 20)
    dim3 gridScores(CHW / 128, CHW / 128, CBT);  // (8, 8, 20)
    dim3 thr(256);

    // 1) spatial GroupNorm
    groupnorm_kernel<<<CBT * CG, thr>>>(x, hn, gamma_s, beta_s);

    // 2) q/k/v projections: A=W [m][k], B=hn [k][n]
    gemm_mma<<<gridConv, thr, SMEM_TOTAL>>>(wq, hn, q, bq, nullptr, CHW, CC, CC, CHW,
                                0, SCHW, SCHW, 0, 1.f, 0, 1, 0, 0);
    gemm_mma<<<gridConv, thr, SMEM_TOTAL>>>(wk, hn, k, bk, nullptr, CHW, CC, CC, CHW,
                                0, SCHW, SCHW, 0, 1.f, 0, 1, 0, 0);
    gemm_mma<<<gridConv, thr, SMEM_TOTAL>>>(wv, hn, v, bv, nullptr, CHW, CC, CC, CHW,
                                0, SCHW, SCHW, 0, 1.f, 0, 1, 0, 0);

    // 3) scores = scale * Q^T K : A=q [k][m], B=k [k][n]
    gemm_mma<<<gridScores, thr, SMEM_TOTAL>>>(q, k, att, nullptr, nullptr, CHW, CC, CHW, CHW,
                                  SCHW, SCHW, SATT, 0, SCALE, 1, 1, 0, 0);

    // 4) softmax over keys
    softmax_kernel<<<CBT * CHW, thr>>>(att);

    // 5) hsp = V * Att^T : A=v [m][k], B=att [n][k]
    gemm_mma<<<gridConv, thr, SMEM_TOTAL>>>(v, att, hsp, nullptr, nullptr, CHW, CHW, CHW, CHW,
                                SCHW, SATT, SCHW, 0, 1.f, 0, 0, 0, 0);

    // 6) spatio = x + Wo*hsp + bo
    gemm_mma<<<gridConv, thr, SMEM_TOTAL>>>(wo, hsp, spatio, bo, x, CHW, CC, CC, CHW,
                                0, SCHW, SCHW, SCHW, 1.f, 0, 1, 0, 0);

    // 7) temporal GroupNorm
    groupnorm_kernel<<<CBT * CG, thr>>>(spatio, hn, gamma_t, beta_t);

    // 8) temporal q/k/v projections, store pixel-major [b][p][t][c]
    gemm_mma<<<gridConv, thr, SMEM_TOTAL>>>(wqt, hn, q, bqt, nullptr, CHW, CC, CC, CHW,
                                0, SCHW, 0, 0, 1.f, 0, 1, 0, 1);
    gemm_mma<<<gridConv, thr, SMEM_TOTAL>>>(wkt, hn, k, bkt, nullptr, CHW, CC, CC, CHW,
                                0, SCHW, 0, 0, 1.f, 0, 1, 0, 1);
    gemm_mma<<<gridConv, thr, SMEM_TOTAL>>>(wvt, hn, v, bvt, nullptr, CHW, CC, CC, CHW,
                                0, SCHW, 0, 0, 1.f, 0, 1, 0, 1);

    // 9) per-pixel temporal attention (htp into hsp, pixel-major)
    temporal_attn_kernel<<<CB * CHW, thr>>>(q, k, v, hsp);

    // 10) out = x + Wot*htp + bot : B=[n][k] rows via pixel-major (ldb=TTC)
    gemm_mma<<<gridConv, thr, SMEM_TOTAL>>>(wot, hsp, out, bot, x, CHW, CC, CC, TTC,
                                0, 0, SCHW, SCHW, 1.f, 0, 0, 1, 0);
}

// round 7
// speedup vs baseline: 5.2281x; 1.0708x over previous
#include <cuda_runtime.h>
#include <cstdint>
#include <math.h>

// ---------------- problem constants ----------------
#define CB   4
#define CT   5
#define CC   512
#define CHW  1024        // H*W
#define CBT  20          // B*T
#define CG   32
#define CPG  16
#define GEPS 1e-6f
#define TTC  (CT*CC)     // 2560 row stride of pixel-major temporal buffers
#define SCALE 0.04419417382415922f   // 512^-0.5

// smem tile geometry (floats)
#define AS0  36          // [m][k] row stride (32 + 4 pad)
#define AS1  136         // [k][m] row stride (128 + 8 pad) -> conflict-free 8*tg+gq
#define TILE_F 4608      // max floats per operand tile (128*36 >= 32*136)
#define STG_F  (2*TILE_F)    // one stage: A + B
#define STG_B  (STG_F*4)     // 36864 bytes
#define NSTAGE 3
#define SMEM_TOTAL (NSTAGE*STG_B)  // 110592 bytes

// ---------------- scratch (device globals) ----------------------------------
static __device__ float g_hn[(size_t)CBT*CC*CHW];
static __device__ float g_q [(size_t)CBT*CC*CHW];
static __device__ float g_k [(size_t)CBT*CC*CHW];
static __device__ float g_v [(size_t)CBT*CC*CHW];
static __device__ float g_att[(size_t)CBT*CHW*CHW];
static __device__ float g_hsp[(size_t)CBT*CC*CHW];
static __device__ float g_spatio[(size_t)CBT*CC*CHW];

// ---------------- small helpers ---------------------------------------------
static __inline__ __device__ float warpSum(float v) {
    #pragma unroll
    for (int o = 16; o > 0; o >>= 1) v += __shfl_xor_sync(0xffffffffu, v, o);
    return v;
}
static __inline__ __device__ float warpMax(float v) {
    #pragma unroll
    for (int o = 16; o > 0; o >>= 1) v = fmaxf(v, __shfl_xor_sync(0xffffffffu, v, o));
    return v;
}
static __device__ __forceinline__ void mma_tf32(float* d, const uint32_t* a, const uint32_t* b) {
    asm volatile(
        "mma.sync.aligned.m16n8k8.row.col.f32.tf32.tf32.f32 "
        "{%0,%1,%2,%3}, {%4,%5,%6,%7}, {%8,%9}, {%0,%1,%2,%3};"
        : "+f"(d[0]), "+f"(d[1]), "+f"(d[2]), "+f"(d[3])
        : "r"(a[0]), "r"(a[1]), "r"(a[2]), "r"(a[3]), "r"(b[0]), "r"(b[1]));
}
static __device__ __forceinline__ void cp16(uint32_t dst, const float* src) {
    asm volatile("cp.async.cg.shared.global [%0], [%1], 16;" :: "r"(dst), "l"(src));
}
static __device__ __forceinline__ void cp_commit() {
    asm volatile("cp.async.commit_group;" ::: "memory");
}
template<int N> static __device__ __forceinline__ void cp_wait() {
    asm volatile("cp.async.wait_group %0;" :: "n"(N) : "memory");
}

// ---------------- tf32 mma.sync GEMM, cp.async multistage, templated ---------
// C[m,n] = alpha * sum_k Aop[m,k] * Bop[k,n]  (+bias[m]) (+resid)
//   TA=0: A gmem [m][k] (ld=lda)   TA=1: A gmem [k][m]
//   TB=0: B gmem [n][k] (ld=ldb)   TB=1: B gmem [k][n]
//   BMODE=1: B batch offset is pixel-major temporal layout
//   CMODE=1: store pixel-major C[n*TTC + m]
template<int TA, int TB, int BMODE, int CMODE>
__global__ __launch_bounds__(256, 2) void gemm_mma(
    const float* __restrict__ A, const float* __restrict__ B, float* __restrict__ Cm,
    const float* __restrict__ bias, const float* __restrict__ resid,
    int N, int K, int lda, int ldb,
    long sA, long sB, long sC, long sR, float alpha)
{
    extern __shared__ float smem[];
    uint32_t sbase = (uint32_t)__cvta_generic_to_shared(smem);

    int tid = threadIdx.x, wid = tid >> 5, lane = tid & 31;
    int gq = lane >> 2, tg = lane & 3;
    int m0 = blockIdx.x * 128, n0 = blockIdx.y * 128, bz = blockIdx.z;
    int mw = (wid & 3) * 32, nw = (wid >> 2) * 64;

    size_t aoff = (size_t)bz * sA;
    size_t boff = BMODE ? (size_t)(bz / CT) * ((size_t)CHW * TTC) + (size_t)(bz % CT) * CC
                        : (size_t)bz * sB;

    float acc[2][8][4];
    #pragma unroll
    for (int mi = 0; mi < 2; mi++)
        #pragma unroll
        for (int ni = 0; ni < 8; ni++)
            #pragma unroll
            for (int c = 0; c < 4; c++) acc[mi][ni][c] = 0.f;

    auto issue = [&](int kc, int buf) {
        int k0 = kc << 5;
        uint32_t sa = sbase + buf * STG_B;
        uint32_t sb = sa + TILE_F * 4;
        #pragma unroll
        for (int i = 0; i < 4; i++) {
            int c = tid + i * 256;
            if (TA == 0) {
                int r = c >> 3, q16 = (c & 7) * 4;
                cp16(sa + (uint32_t)(r * AS0 + q16) * 4,
                     A + aoff + (size_t)(m0 + r) * lda + k0 + q16);
            } else {
                int r = c >> 5, off = (c & 31) * 4;
                cp16(sa + (uint32_t)(r * AS1 + off) * 4,
                     A + aoff + (size_t)(k0 + r) * lda + m0 + off);
            }
        }
        #pragma unroll
        for (int i = 0; i < 4; i++) {
            int c = tid + i * 256;
            if (TB == 0) {
                int r = c >> 3, q16 = (c & 7) * 4;
                cp16(sb + (uint32_t)(r * AS0 + q16) * 4,
                     B + boff + (size_t)(n0 + r) * ldb + k0 + q16);
            } else {
                int r = c >> 5, off = (c & 31) * 4;
                cp16(sb + (uint32_t)(r * AS1 + off) * 4,
                     B + boff + (size_t)(k0 + r) * ldb + n0 + off);
            }
        }
        cp_commit();
    };

    int NC = K >> 5;
    issue(0, 0);
    issue(1, 1);

    int buf = 0;
    for (int kc = 0; kc < NC; kc++) {
        if (kc == NC - 1) cp_wait<0>(); else cp_wait<1>();
        __syncthreads();
        // issue into the retired buffer (all warps are past it per the barrier)
        if (kc + 2 < NC) issue(kc + 2, buf == 0 ? 2 : buf - 1);

        const float* sA_ = smem + buf * STG_F;
        const float* sB_ = sA_ + TILE_F;

        #pragma unroll
        for (int ks = 0; ks < 4; ks++) {
            int kb = ks * 8;
            uint32_t af[2][4];
            #pragma unroll
            for (int mi = 0; mi < 2; mi++) {
                int mr = mw + mi * 16 + gq;
                if (TA == 0) {
                    af[mi][0] = __float_as_uint(sA_[(mr)     * AS0 + kb + tg]);
                    af[mi][1] = __float_as_uint(sA_[(mr + 8) * AS0 + kb + tg]);
                    af[mi][2] = __float_as_uint(sA_[(mr)     * AS0 + kb + tg + 4]);
                    af[mi][3] = __float_as_uint(sA_[(mr + 8) * AS0 + kb + tg + 4]);
                } else {
                    af[mi][0] = __float_as_uint(sA_[(kb + tg)     * AS1 + mr]);
                    af[mi][1] = __float_as_uint(sA_[(kb + tg)     * AS1 + mr + 8]);
                    af[mi][2] = __float_as_uint(sA_[(kb + tg + 4) * AS1 + mr]);
                    af[mi][3] = __float_as_uint(sA_[(kb + tg + 4) * AS1 + mr + 8]);
                }
            }
            uint32_t bf[8][2];
            #pragma unroll
            for (int ni = 0; ni < 8; ni++) {
                int nn = nw + ni * 8 + gq;
                if (TB == 0) {
                    bf[ni][0] = __float_as_uint(sB_[nn * AS0 + kb + tg]);
                    bf[ni][1] = __float_as_uint(sB_[nn * AS0 + kb + tg + 4]);
                } else {
                    bf[ni][0] = __float_as_uint(sB_[(kb + tg)     * AS1 + nn]);
                    bf[ni][1] = __float_as_uint(sB_[(kb + tg + 4) * AS1 + nn]);
                }
            }
            #pragma unroll
            for (int mi = 0; mi < 2; mi++)
                #pragma unroll
                for (int ni = 0; ni < 8; ni++)
                    mma_tf32(acc[mi][ni], af[mi], bf[ni]);
        }
        buf = (buf == NSTAGE - 1) ? 0 : buf + 1;
    }

    // ---- epilogue ----
    if (CMODE == 0) {
        size_t coff = (size_t)bz * sC;
        size_t roff = (size_t)bz * sR;
        #pragma unroll
        for (int mi = 0; mi < 2; mi++) {
            #pragma unroll
            for (int half = 0; half < 2; half++) {
                int m = m0 + mw + mi * 16 + gq + half * 8;
                float bv = bias ? bias[m] : 0.f;
                #pragma unroll
                for (int ni = 0; ni < 8; ni++) {
                    int n = n0 + nw + ni * 8 + tg * 2;
                    float v0 = acc[mi][ni][half * 2 + 0] * alpha + bv;
                    float v1 = acc[mi][ni][half * 2 + 1] * alpha + bv;
                    if (resid) {
                        v0 += resid[roff + (size_t)m * N + n];
                        v1 += resid[roff + (size_t)m * N + n + 1];
                    }
                    *(float2*)(Cm + coff + (size_t)m * N + n) = make_float2(v0, v1);
                }
            }
        }
    } else {
        size_t coff = (size_t)(bz / CT) * ((size_t)CHW * TTC) + (size_t)(bz % CT) * CC;
        #pragma unroll
        for (int mi = 0; mi < 2; mi++) {
            #pragma unroll
            for (int half = 0; half < 2; half++) {
                int m = m0 + mw + mi * 16 + gq + half * 8;
                float bv = bias ? bias[m] : 0.f;
                #pragma unroll
                for (int ni = 0; ni < 8; ni++) {
                    int n = n0 + nw + ni * 8 + tg * 2;
                    Cm[coff + (size_t)n * TTC + m]       = acc[mi][ni][half * 2 + 0] * alpha + bv;
                    Cm[coff + (size_t)(n + 1) * TTC + m] = acc[mi][ni][half * 2 + 1] * alpha + bv;
                }
            }
        }
    }
}

// ---------------- GroupNorm --------------------------------------------------
__global__ __launch_bounds__(256) void groupnorm_kernel(
    const float* __restrict__ x, float* __restrict__ out,
    const float* __restrict__ gamma, const float* __restrict__ beta)
{
    const int GSZ = CPG * CHW;
    int n = blockIdx.x / CG, g = blockIdx.x % CG;
    size_t base = (size_t)n * CC * CHW + (size_t)g * GSZ;
    int tid = threadIdx.x, lane = tid & 31, wid = tid >> 5;

    float s = 0.f, s2 = 0.f;
    for (int i = tid; i < GSZ; i += 256) {
        float v = x[base + i];
        s += v; s2 += v * v;
    }
    __shared__ float rs[8], rs2[8];
    s = warpSum(s); s2 = warpSum(s2);
    if (lane == 0) { rs[wid] = s; rs2[wid] = s2; }
    __syncthreads();
    if (tid == 0) {
        float S = 0.f, S2 = 0.f;
        #pragma unroll
        for (int w = 0; w < 8; w++) { S += rs[w]; S2 += rs2[w]; }
        rs[0] = S; rs2[0] = S2;
    }
    __syncthreads();
    float mu = rs[0] / (float)GSZ;
    float var = rs2[0] / (float)GSZ - mu * mu;
    float rstd = rsqrtf(var + GEPS);

    for (int i = tid; i < GSZ; i += 256) {
        int c = g * CPG + (i >> 10);
        out[base + i] = (x[base + i] - mu) * rstd * gamma[c] + beta[c];
    }
}

// ---------------- softmax over rows of 1024 ---------------------------------
__global__ __launch_bounds__(256) void softmax_kernel(float* __restrict__ att)
{
    size_t row = (size_t)blockIdx.x * CHW;
    __shared__ float buf[CHW];
    __shared__ float red[8];
    int tid = threadIdx.x, lane = tid & 31, wid = tid >> 5;

    float mx = -3.4e38f;
    #pragma unroll
    for (int r = 0; r < CHW / 256; r++) {
        int i = tid + r * 256;
        float v = att[row + i];
        buf[i] = v;
        mx = fmaxf(mx, v);
    }
    mx = warpMax(mx);
    if (lane == 0) red[wid] = mx;
    __syncthreads();
    if (tid == 0) {
        float m = red[0];
        #pragma unroll
        for (int w = 1; w < 8; w++) m = fmaxf(m, red[w]);
        red[0] = m;
    }
    __syncthreads();
    mx = red[0];
    __syncthreads();

    float s = 0.f;
    #pragma unroll
    for (int r = 0; r < CHW / 256; r++) {
        int i = tid + r * 256;
        float e = __expf(buf[i] - mx);
        buf[i] = e;
        s += e;
    }
    s = warpSum(s);
    if (lane == 0) red[wid] = s;
    __syncthreads();
    if (tid == 0) {
        float S = 0.f;
        #pragma unroll
        for (int w = 0; w < 8; w++) S += red[w];
        red[0] = S;
    }
    __syncthreads();
    float inv = 1.f / red[0];
    #pragma unroll
    for (int r = 0; r < CHW / 256; r++) {
        int i = tid + r * 256;
        att[row + i] = buf[i] * inv;
    }
}

// ---------------- temporal attention ----------------------------------------
__global__ __launch_bounds__(256) void temporal_attn_kernel(
    const float* __restrict__ q, const float* __restrict__ k,
    const float* __restrict__ v, float* __restrict__ o)
{
    size_t base = (size_t)blockIdx.x * TTC;
    int tid = threadIdx.x, lane = tid & 31;

    __shared__ float sacc[CT * CT];
    __shared__ float satt[CT][CT];
    if (tid < CT * CT) sacc[tid] = 0.f;

    float qr[2][CT], kr[2][CT], vr[2][CT];
    float acc[CT][CT] = {};

    #pragma unroll
    for (int r = 0; r < 2; r++) {
        int c = tid + r * 256;
        #pragma unroll
        for (int t = 0; t < CT; t++) {
            qr[r][t] = q[base + t * CC + c];
            kr[r][t] = k[base + t * CC + c];
            vr[r][t] = v[base + t * CC + c];
        }
        #pragma unroll
        for (int t = 0; t < CT; t++)
            #pragma unroll
            for (int s = 0; s < CT; s++)
                acc[t][s] = fmaf(qr[r][t], kr[r][s], acc[t][s]);
    }
    __syncthreads();

    #pragma unroll
    for (int t = 0; t < CT; t++)
        #pragma unroll
        for (int s = 0; s < CT; s++) {
            float p = warpSum(acc[t][s]);
            if (lane == 0) atomicAdd(&sacc[t * CT + s], p);
        }
    __syncthreads();

    if (tid < CT) {
        float mx = -3.4e38f;
        #pragma unroll
        for (int s = 0; s < CT; s++) mx = fmaxf(mx, sacc[tid * CT + s] * SCALE);
        float sum = 0.f;
        #pragma unroll
        for (int s = 0; s < CT; s++) {
            float e = __expf(sacc[tid * CT + s] * SCALE - mx);
            satt[tid][s] = e;
            sum += e;
        }
        float inv = 1.f / sum;
        #pragma unroll
        for (int s = 0; s < CT; s++) satt[tid][s] *= inv;
    }
    __syncthreads();

    #pragma unroll
    for (int r = 0; r < 2; r++) {
        int c = tid + r * 256;
        #pragma unroll
        for (int t = 0; t < CT; t++) {
            float ov = 0.f;
            #pragma unroll
            for (int s = 0; s < CT; s++) ov = fmaf(satt[t][s], vr[r][s], ov);
            o[base + t * CC + c] = ov;
        }
    }
}

// ---------------- launch ----------------------------------------------------
extern "C" void kernel_launch(void* const* d_in, const int* in_sizes, int n_in,
                              void* d_out, int out_size)
{
    const float* x     = (const float*)d_in[0];
    const float* wq    = (const float*)d_in[1];
    const float* bq    = (const float*)d_in[2];
    const float* wk    = (const float*)d_in[3];
    const float* bk    = (const float*)d_in[4];
    const float* wv    = (const float*)d_in[5];
    const float* bv    = (const float*)d_in[6];
    const float* wo    = (const float*)d_in[7];
    const float* bo    = (const float*)d_in[8];
    const float* wqt   = (const float*)d_in[9];
    const float* bqt   = (const float*)d_in[10];
    const float* wkt   = (const float*)d_in[11];
    const float* bkt   = (const float*)d_in[12];
    const float* wvt   = (const float*)d_in[13];
    const float* bvt   = (const float*)d_in[14];
    const float* wot   = (const float*)d_in[15];
    const float* bot   = (const float*)d_in[16];
    const float* gamma_s = (const float*)d_in[17];
    const float* beta_s  = (const float*)d_in[18];
    const float* gamma_t = (const float*)d_in[19];
    const float* beta_t  = (const float*)d_in[20];
    float* out = (float*)d_out;

    float *hn, *q, *k, *v, *att, *hsp, *spatio;
    cudaGetSymbolAddress((void**)&hn,     g_hn);
    cudaGetSymbolAddress((void**)&q,      g_q);
    cudaGetSymbolAddress((void**)&k,      g_k);
    cudaGetSymbolAddress((void**)&v,      g_v);
    cudaGetSymbolAddress((void**)&att,    g_att);
    cudaGetSymbolAddress((void**)&hsp,    g_hsp);
    cudaGetSymbolAddress((void**)&spatio, g_spatio);

    cudaFuncSetAttribute(gemm_mma<0,1,0,0>, cudaFuncAttributeMaxDynamicSharedMemorySize, SMEM_TOTAL);
    cudaFuncSetAttribute(gemm_mma<1,1,0,0>, cudaFuncAttributeMaxDynamicSharedMemorySize, SMEM_TOTAL);
    cudaFuncSetAttribute(gemm_mma<0,0,0,0>, cudaFuncAttributeMaxDynamicSharedMemorySize, SMEM_TOTAL);
    cudaFuncSetAttribute(gemm_mma<0,1,0,1>, cudaFuncAttributeMaxDynamicSharedMemorySize, SMEM_TOTAL);
    cudaFuncSetAttribute(gemm_mma<0,0,1,0>, cudaFuncAttributeMaxDynamicSharedMemorySize, SMEM_TOTAL);

    const long SCHW = (long)CC * CHW;
    const long SATT = (long)CHW * CHW;

    dim3 gridConv(CC / 128, CHW / 128, CBT);     // (4, 8, 20)
    dim3 gridScores(CHW / 128, CHW / 128, CBT);  // (8, 8, 20)
    dim3 thr(256);

    // 1) spatial GroupNorm
    groupnorm_kernel<<<CBT * CG, thr>>>(x, hn, gamma_s, beta_s);

    // 2) q/k/v projections: A=W [m][k], B=hn [k][n]
    gemm_mma<0,1,0,0><<<gridConv, thr, SMEM_TOTAL>>>(wq, hn, q, bq, nullptr, CHW, CC, CC, CHW,
                                0, SCHW, SCHW, 0, 1.f);
    gemm_mma<0,1,0,0><<<gridConv, thr, SMEM_TOTAL>>>(wk, hn, k, bk, nullptr, CHW, CC, CC, CHW,
                                0, SCHW, SCHW, 0, 1.f);
    gemm_mma<0,1,0,0><<<gridConv, thr, SMEM_TOTAL>>>(wv, hn, v, bv, nullptr, CHW, CC, CC, CHW,
                                0, SCHW, SCHW, 0, 1.f);

    // 3) scores = scale * Q^T K : A=q [k][m], B=k [k][n]
    gemm_mma<1,1,0,0><<<gridScores, thr, SMEM_TOTAL>>>(q, k, att, nullptr, nullptr, CHW, CC, CHW, CHW,
                                  SCHW, SCHW, SATT, 0, SCALE);

    // 4) softmax over keys
    softmax_kernel<<<CBT * CHW, thr>>>(att);

    // 5) hsp = V * Att^T : A=v [m][k], B=att [n][k]
    gemm_mma<0,0,0,0><<<gridConv, thr, SMEM_TOTAL>>>(v, att, hsp, nullptr, nullptr, CHW, CHW, CHW, CHW,
                                SCHW, SATT, SCHW, 0, 1.f);

    // 6) spatio = x + Wo*hsp + bo
    gemm_mma<0,1,0,0><<<gridConv, thr, SMEM_TOTAL>>>(wo, hsp, spatio, bo, x, CHW, CC, CC, CHW,
                                0, SCHW, SCHW, SCHW, 1.f);

    // 7) temporal GroupNorm
    groupnorm_kernel<<<CBT * CG, thr>>>(spatio, hn, gamma_t, beta_t);

    // 8) temporal q/k/v projections, store pixel-major [b][p][t][c]
    gemm_mma<0,1,0,1><<<gridConv, thr, SMEM_TOTAL>>>(wqt, hn, q, bqt, nullptr, CHW, CC, CC, CHW,
                                0, SCHW, 0, 0, 1.f);
    gemm_mma<0,1,0,1><<<gridConv, thr, SMEM_TOTAL>>>(wkt, hn, k, bkt, nullptr, CHW, CC, CC, CHW,
                                0, SCHW, 0, 0, 1.f);
    gemm_mma<0,1,0,1><<<gridConv, thr, SMEM_TOTAL>>>(wvt, hn, v, bvt, nullptr, CHW, CC, CC, CHW,
                                0, SCHW, 0, 0, 1.f);

    // 9) per-pixel temporal attention (htp into hsp, pixel-major)
    temporal_attn_kernel<<<CB * CHW, thr>>>(q, k, v, hsp);

    // 10) out = x + Wot*htp + bot : B=[n][k] rows via pixel-major (ldb=TTC)
    gemm_mma<0,0,1,0><<<gridConv, thr, SMEM_TOTAL>>>(wot, hsp, out, bot, x, CHW, CC, CC, TTC,
                                0, 0, SCHW, SCHW, 1.f);
}

// round 8
// speedup vs baseline: 8.6003x; 1.6450x over previous
#include <cuda_runtime.h>
#include <cuda_bf16.h>
#include <cstdint>
#include <math.h>

// ---------------- problem constants ----------------
#define CB   4
#define CT   5
#define CC   512
#define CHW  1024        // H*W
#define CBT  20          // B*T
#define CG   32
#define CPG  16
#define GEPS 1e-6f
#define TTC  (CT*CC)     // 2560 row stride of pixel-major temporal buffers
#define SCALE 0.04419417382415922f   // 512^-0.5

// smem tile geometry (bytes): k-chunk = 32 bf16 = 64B rows
#define RS0  80          // row-major tile row stride: 64B + 16B pad (128 rows)
#define RS1  272         // k-major tile row stride: 256B + 16B pad (32 rows)
#define SLAB 10240       // per-operand slab: max(128*80, 32*272)
#define STG_B (2*SLAB)   // 20480 per stage (A + B)
#define NSTAGE 4
#define SMEM_TOTAL (NSTAGE*STG_B)   // 81920

// ---------------- scratch (device globals) ----------------------------------
static __device__ __nv_bfloat16 g_wb [(size_t)8*CC*CC];        // 8 weights bf16
static __device__ __nv_bfloat16 g_hnb[(size_t)CBT*CC*CHW];
static __device__ __nv_bfloat16 g_qb [(size_t)CBT*CC*CHW];
static __device__ __nv_bfloat16 g_kb [(size_t)CBT*CC*CHW];
static __device__ __nv_bfloat16 g_vb [(size_t)CBT*CC*CHW];
static __device__ __nv_bfloat16 g_attb[(size_t)CBT*CHW*CHW];
static __device__ __nv_bfloat16 g_hspb[(size_t)CBT*CC*CHW];
static __device__ float g_attf[(size_t)CBT*CHW*CHW];
static __device__ float g_spatio[(size_t)CBT*CC*CHW];

// ---------------- small helpers ---------------------------------------------
static __inline__ __device__ float warpSum(float v) {
    #pragma unroll
    for (int o = 16; o > 0; o >>= 1) v += __shfl_xor_sync(0xffffffffu, v, o);
    return v;
}
static __inline__ __device__ float warpMax(float v) {
    #pragma unroll
    for (int o = 16; o > 0; o >>= 1) v = fmaxf(v, __shfl_xor_sync(0xffffffffu, v, o));
    return v;
}
static __device__ __forceinline__ void mma_bf16(float* d, const uint32_t* a, const uint32_t* b) {
    asm volatile(
        "mma.sync.aligned.m16n8k16.row.col.f32.bf16.bf16.f32 "
        "{%0,%1,%2,%3}, {%4,%5,%6,%7}, {%8,%9}, {%0,%1,%2,%3};"
        : "+f"(d[0]), "+f"(d[1]), "+f"(d[2]), "+f"(d[3])
        : "r"(a[0]), "r"(a[1]), "r"(a[2]), "r"(a[3]), "r"(b[0]), "r"(b[1]));
}
static __device__ __forceinline__ void ldsm4(uint32_t& r0, uint32_t& r1, uint32_t& r2, uint32_t& r3, uint32_t a) {
    asm volatile("ldmatrix.sync.aligned.m8n8.x4.shared.b16 {%0,%1,%2,%3}, [%4];"
                 : "=r"(r0), "=r"(r1), "=r"(r2), "=r"(r3) : "r"(a));
}
static __device__ __forceinline__ void ldsm4t(uint32_t& r0, uint32_t& r1, uint32_t& r2, uint32_t& r3, uint32_t a) {
    asm volatile("ldmatrix.sync.aligned.m8n8.x4.trans.shared.b16 {%0,%1,%2,%3}, [%4];"
                 : "=r"(r0), "=r"(r1), "=r"(r2), "=r"(r3) : "r"(a));
}
static __device__ __forceinline__ void cp16(uint32_t dst, const void* src) {
    asm volatile("cp.async.cg.shared.global [%0], [%1], 16;" :: "r"(dst), "l"(src));
}
static __device__ __forceinline__ void cp_commit() {
    asm volatile("cp.async.commit_group;" ::: "memory");
}
template<int N> static __device__ __forceinline__ void cp_wait() {
    asm volatile("cp.async.wait_group %0;" :: "n"(N) : "memory");
}

// ---------------- bf16 m16n8k16 GEMM, ldmatrix + cp.async 4-stage ------------
// C[m,n] = alpha * sum_k Aop[m,k] * Bop[k,n]  (+bias[m]) (+resid)
//   TA=0: A gmem [m][k] (ld=lda)   TA=1: A gmem [k][m]
//   TB=0: B gmem [n][k] (ld=ldb)   TB=1: B gmem [k][n]
//   BMODE=1: B batch offset is pixel-major temporal layout
//   CMODE=1: store pixel-major C[n*TTC + m] (bf16)
//   OBF=1: output bf16, else fp32
template<int TA, int TB, int BMODE, int CMODE, int OBF>
__global__ __launch_bounds__(256, 2) void gemm_bf(
    const __nv_bfloat16* __restrict__ A, const __nv_bfloat16* __restrict__ B, void* __restrict__ Cvp,
    const float* __restrict__ bias, const float* __restrict__ resid,
    int N, int K, int lda, int ldb,
    long sA, long sB, long sC, long sR, float alpha)
{
    extern __shared__ char smem[];
    uint32_t sbase = (uint32_t)__cvta_generic_to_shared(smem);

    int tid = threadIdx.x, wid = tid >> 5, lane = tid & 31;
    int gq = lane >> 2, tg = lane & 3;
    int m0 = blockIdx.x * 128, n0 = blockIdx.y * 128, bz = blockIdx.z;
    int mw = (wid & 3) * 32, nw = (wid >> 2) * 64;

    size_t aoff = (size_t)bz * sA;
    size_t boff = BMODE ? (size_t)(bz / CT) * ((size_t)CHW * TTC) + (size_t)(bz % CT) * CC
                        : (size_t)bz * sB;

    float acc[2][8][4];
    #pragma unroll
    for (int mi = 0; mi < 2; mi++)
        #pragma unroll
        for (int ni = 0; ni < 8; ni++)
            #pragma unroll
            for (int c = 0; c < 4; c++) acc[mi][ni][c] = 0.f;

    auto issue = [&](int kc, int buf) {
        int k0 = kc << 5;
        uint32_t sa = sbase + buf * STG_B;
        uint32_t sb = sa + SLAB;
        #pragma unroll
        for (int i = 0; i < 2; i++) {
            int c = tid + i * 256;
            if (TA == 0) {
                int r = c >> 2, ch = c & 3;
                cp16(sa + (uint32_t)(r * RS0 + ch * 16),
                     A + aoff + (size_t)(m0 + r) * lda + k0 + ch * 8);
            } else {
                int r = c >> 4, ch = c & 15;
                cp16(sa + (uint32_t)(r * RS1 + ch * 16),
                     A + aoff + (size_t)(k0 + r) * lda + m0 + ch * 8);
            }
        }
        #pragma unroll
        for (int i = 0; i < 2; i++) {
            int c = tid + i * 256;
            if (TB == 0) {
                int r = c >> 2, ch = c & 3;
                cp16(sb + (uint32_t)(r * RS0 + ch * 16),
                     B + boff + (size_t)(n0 + r) * ldb + k0 + ch * 8);
            } else {
                int r = c >> 4, ch = c & 15;
                cp16(sb + (uint32_t)(r * RS1 + ch * 16),
                     B + boff + (size_t)(k0 + r) * ldb + n0 + ch * 8);
            }
        }
        cp_commit();
    };

    int NC = K >> 5;
    issue(0, 0); issue(1, 1); issue(2, 2);

    // ldmatrix lane decomposition: mat = lane>>3
    int l7 = lane & 7;
    int sel8 = ((lane >> 3) & 1) * 8;   // mat&1
    int sel16 = (lane >> 4) * 8;        // mat>>1

    for (int kc = 0; kc < NC; kc++) {
        cp_wait<2>();
        __syncthreads();
        if (kc + 3 < NC) issue(kc + 3, (kc + 3) & 3);

        uint32_t sa = sbase + (kc & 3) * STG_B;
        uint32_t sb = sa + SLAB;

        #pragma unroll
        for (int ks = 0; ks < 2; ks++) {
            int kb = ks * 16;
            uint32_t af[2][4];
            #pragma unroll
            for (int mi = 0; mi < 2; mi++) {
                if (TA == 0) {
                    // matrices: (m-lo,k-lo),(m-hi,k-lo),(m-lo,k-hi),(m-hi,k-hi)
                    uint32_t addr = sa + (uint32_t)((mw + mi * 16 + l7 + sel8) * RS0 + (kb + sel16) * 2);
                    ldsm4(af[mi][0], af[mi][1], af[mi][2], af[mi][3], addr);
                } else {
                    uint32_t addr = sa + (uint32_t)((kb + sel16 + l7) * RS1 + (mw + mi * 16 + sel8) * 2);
                    ldsm4t(af[mi][0], af[mi][1], af[mi][2], af[mi][3], addr);
                }
            }
            uint32_t bf[8][2];
            #pragma unroll
            for (int j2 = 0; j2 < 4; j2++) {
                uint32_t r0, r1, r2, r3;
                if (TB == 0) {
                    // matrices: (n_j,k-lo),(n_j,k-hi),(n_j+1,k-lo),(n_j+1,k-hi)
                    uint32_t addr = sb + (uint32_t)((nw + j2 * 16 + sel16 + l7) * RS0 + (kb + sel8) * 2);
                    ldsm4(r0, r1, r2, r3, addr);
                } else {
                    uint32_t addr = sb + (uint32_t)((kb + sel8 + l7) * RS1 + (nw + j2 * 16 + sel16) * 2);
                    ldsm4t(r0, r1, r2, r3, addr);
                }
                bf[j2 * 2 + 0][0] = r0; bf[j2 * 2 + 0][1] = r1;
                bf[j2 * 2 + 1][0] = r2; bf[j2 * 2 + 1][1] = r3;
            }
            #pragma unroll
            for (int mi = 0; mi < 2; mi++)
                #pragma unroll
                for (int ni = 0; ni < 8; ni++)
                    mma_bf16(acc[mi][ni], af[mi], bf[ni]);
        }
    }

    // ---- epilogue ----
    if (CMODE == 0) {
        size_t coff = (size_t)bz * sC;
        size_t roff = (size_t)bz * sR;
        #pragma unroll
        for (int mi = 0; mi < 2; mi++) {
            #pragma unroll
            for (int half = 0; half < 2; half++) {
                int m = m0 + mw + mi * 16 + gq + half * 8;
                float bv = bias ? bias[m] : 0.f;
                #pragma unroll
                for (int ni = 0; ni < 8; ni++) {
                    int n = n0 + nw + ni * 8 + tg * 2;
                    float v0 = acc[mi][ni][half * 2 + 0] * alpha + bv;
                    float v1 = acc[mi][ni][half * 2 + 1] * alpha + bv;
                    if (resid) {
                        v0 += resid[roff + (size_t)m * N + n];
                        v1 += resid[roff + (size_t)m * N + n + 1];
                    }
                    if (OBF) {
                        __nv_bfloat162 p = __floats2bfloat162_rn(v0, v1);
                        *(__nv_bfloat162*)((__nv_bfloat16*)Cvp + coff + (size_t)m * N + n) = p;
                    } else {
                        *(float2*)((float*)Cvp + coff + (size_t)m * N + n) = make_float2(v0, v1);
                    }
                }
            }
        }
    } else {
        size_t coff = (size_t)(bz / CT) * ((size_t)CHW * TTC) + (size_t)(bz % CT) * CC;
        __nv_bfloat16* Cb = (__nv_bfloat16*)Cvp;
        #pragma unroll
        for (int mi = 0; mi < 2; mi++) {
            #pragma unroll
            for (int half = 0; half < 2; half++) {
                int m = m0 + mw + mi * 16 + gq + half * 8;
                float bv = bias ? bias[m] : 0.f;
                #pragma unroll
                for (int ni = 0; ni < 8; ni++) {
                    int n = n0 + nw + ni * 8 + tg * 2;
                    Cb[coff + (size_t)n * TTC + m]       = __float2bfloat16_rn(acc[mi][ni][half * 2 + 0] * alpha + bv);
                    Cb[coff + (size_t)(n + 1) * TTC + m] = __float2bfloat16_rn(acc[mi][ni][half * 2 + 1] * alpha + bv);
                }
            }
        }
    }
}

// ---------------- weight fp32 -> bf16 ----------------------------------------
__global__ __launch_bounds__(256) void cvt_weights(
    const float* w0, const float* w1, const float* w2, const float* w3,
    const float* w4, const float* w5, const float* w6, const float* w7,
    __nv_bfloat16* dst)
{
    int idx = blockIdx.x * 256 + threadIdx.x;      // 0 .. 262143
    int w = blockIdx.y;
    const float* src;
    switch (w) {
        case 0: src = w0; break; case 1: src = w1; break;
        case 2: src = w2; break; case 3: src = w3; break;
        case 4: src = w4; break; case 5: src = w5; break;
        case 6: src = w6; break; default: src = w7; break;
    }
    dst[(size_t)w * CC * CC + idx] = __float2bfloat16_rn(src[idx]);
}

// ---------------- GroupNorm (fp32 in -> bf16 out) ----------------------------
__global__ __launch_bounds__(256) void groupnorm_kernel(
    const float* __restrict__ x, __nv_bfloat16* __restrict__ out,
    const float* __restrict__ gamma, const float* __restrict__ beta)
{
    const int GSZ = CPG * CHW;
    int n = blockIdx.x / CG, g = blockIdx.x % CG;
    size_t base = (size_t)n * CC * CHW + (size_t)g * GSZ;
    int tid = threadIdx.x, lane = tid & 31, wid = tid >> 5;

    float s = 0.f, s2 = 0.f;
    for (int i = tid; i < GSZ; i += 256) {
        float v = x[base + i];
        s += v; s2 += v * v;
    }
    __shared__ float rs[8], rs2[8];
    s = warpSum(s); s2 = warpSum(s2);
    if (lane == 0) { rs[wid] = s; rs2[wid] = s2; }
    __syncthreads();
    if (tid == 0) {
        float S = 0.f, S2 = 0.f;
        #pragma unroll
        for (int w = 0; w < 8; w++) { S += rs[w]; S2 += rs2[w]; }
        rs[0] = S; rs2[0] = S2;
    }
    __syncthreads();
    float mu = rs[0] / (float)GSZ;
    float var = rs2[0] / (float)GSZ - mu * mu;
    float rstd = rsqrtf(var + GEPS);

    for (int i = tid; i < GSZ; i += 256) {
        int c = g * CPG + (i >> 10);
        out[base + i] = __float2bfloat16_rn((x[base + i] - mu) * rstd * gamma[c] + beta[c]);
    }
}

// ---------------- softmax (fp32 in -> bf16 out) ------------------------------
__global__ __launch_bounds__(256) void softmax_kernel(
    const float* __restrict__ att, __nv_bfloat16* __restrict__ out)
{
    size_t row = (size_t)blockIdx.x * CHW;
    __shared__ float buf[CHW];
    __shared__ float red[8];
    int tid = threadIdx.x, lane = tid & 31, wid = tid >> 5;

    float mx = -3.4e38f;
    #pragma unroll
    for (int r = 0; r < CHW / 256; r++) {
        int i = tid + r * 256;
        float v = att[row + i];
        buf[i] = v;
        mx = fmaxf(mx, v);
    }
    mx = warpMax(mx);
    if (lane == 0) red[wid] = mx;
    __syncthreads();
    if (tid == 0) {
        float m = red[0];
        #pragma unroll
        for (int w = 1; w < 8; w++) m = fmaxf(m, red[w]);
        red[0] = m;
    }
    __syncthreads();
    mx = red[0];
    __syncthreads();

    float s = 0.f;
    #pragma unroll
    for (int r = 0; r < CHW / 256; r++) {
        int i = tid + r * 256;
        float e = __expf(buf[i] - mx);
        buf[i] = e;
        s += e;
    }
    s = warpSum(s);
    if (lane == 0) red[wid] = s;
    __syncthreads();
    if (tid == 0) {
        float S = 0.f;
        #pragma unroll
        for (int w = 0; w < 8; w++) S += red[w];
        red[0] = S;
    }
    __syncthreads();
    float inv = 1.f / red[0];
    #pragma unroll
    for (int r = 0; r < CHW / 256; r++) {
        int i = tid + r * 256;
        out[row + i] = __float2bfloat16_rn(buf[i] * inv);
    }
}

// ---------------- temporal attention (bf16 pixel-major) ----------------------
__global__ __launch_bounds__(256) void temporal_attn_kernel(
    const __nv_bfloat16* __restrict__ q, const __nv_bfloat16* __restrict__ k,
    const __nv_bfloat16* __restrict__ v, __nv_bfloat16* __restrict__ o)
{
    size_t base = (size_t)blockIdx.x * TTC;
    int tid = threadIdx.x, lane = tid & 31;

    __shared__ float sacc[CT * CT];
    __shared__ float satt[CT][CT];
    if (tid < CT * CT) sacc[tid] = 0.f;

    float qr[2][CT], kr[2][CT], vr[2][CT];
    float acc[CT][CT] = {};

    #pragma unroll
    for (int r = 0; r < 2; r++) {
        int c = tid + r * 256;
        #pragma unroll
        for (int t = 0; t < CT; t++) {
            qr[r][t] = __bfloat162float(q[base + t * CC + c]);
            kr[r][t] = __bfloat162float(k[base + t * CC + c]);
            vr[r][t] = __bfloat162float(v[base + t * CC + c]);
        }
        #pragma unroll
        for (int t = 0; t < CT; t++)
            #pragma unroll
            for (int s = 0; s < CT; s++)
                acc[t][s] = fmaf(qr[r][t], kr[r][s], acc[t][s]);
    }
    __syncthreads();

    #pragma unroll
    for (int t = 0; t < CT; t++)
        #pragma unroll
        for (int s = 0; s < CT; s++) {
            float p = warpSum(acc[t][s]);
            if (lane == 0) atomicAdd(&sacc[t * CT + s], p);
        }
    __syncthreads();

    if (tid < CT) {
        float mx = -3.4e38f;
        #pragma unroll
        for (int s = 0; s < CT; s++) mx = fmaxf(mx, sacc[tid * CT + s] * SCALE);
        float sum = 0.f;
        #pragma unroll
        for (int s = 0; s < CT; s++) {
            float e = __expf(sacc[tid * CT + s] * SCALE - mx);
            satt[tid][s] = e;
            sum += e;
        }
        float inv = 1.f / sum;
        #pragma unroll
        for (int s = 0; s < CT; s++) satt[tid][s] *= inv;
    }
    __syncthreads();

    #pragma unroll
    for (int r = 0; r < 2; r++) {
        int c = tid + r * 256;
        #pragma unroll
        for (int t = 0; t < CT; t++) {
            float ov = 0.f;
            #pragma unroll
            for (int s = 0; s < CT; s++) ov = fmaf(satt[t][s], vr[r][s], ov);
            o[base + t * CC + c] = __float2bfloat16_rn(ov);
        }
    }
}

// ---------------- launch ----------------------------------------------------
extern "C" void kernel_launch(void* const* d_in, const int* in_sizes, int n_in,
                              void* d_out, int out_size)
{
    const float* x     = (const float*)d_in[0];
    const float* wq    = (const float*)d_in[1];
    const float* bq    = (const float*)d_in[2];
    const float* wk    = (const float*)d_in[3];
    const float* bk    = (const float*)d_in[4];
    const float* wv    = (const float*)d_in[5];
    const float* bv    = (const float*)d_in[6];
    const float* wo    = (const float*)d_in[7];
    const float* bo    = (const float*)d_in[8];
    const float* wqt   = (const float*)d_in[9];
    const float* bqt   = (const float*)d_in[10];
    const float* wkt   = (const float*)d_in[11];
    const float* bkt   = (const float*)d_in[12];
    const float* wvt   = (const float*)d_in[13];
    const float* bvt   = (const float*)d_in[14];
    const float* wot   = (const float*)d_in[15];
    const float* bot   = (const float*)d_in[16];
    const float* gamma_s = (const float*)d_in[17];
    const float* beta_s  = (const float*)d_in[18];
    const float* gamma_t = (const float*)d_in[19];
    const float* beta_t  = (const float*)d_in[20];
    float* out = (float*)d_out;

    __nv_bfloat16 *wb, *hnb, *qb, *kb, *vb, *attb, *hspb;
    float *attf, *spatio;
    cudaGetSymbolAddress((void**)&wb,    g_wb);
    cudaGetSymbolAddress((void**)&hnb,   g_hnb);
    cudaGetSymbolAddress((void**)&qb,    g_qb);
    cudaGetSymbolAddress((void**)&kb,    g_kb);
    cudaGetSymbolAddress((void**)&vb,    g_vb);
    cudaGetSymbolAddress((void**)&attb,  g_attb);
    cudaGetSymbolAddress((void**)&hspb,  g_hspb);
    cudaGetSymbolAddress((void**)&attf,  g_attf);
    cudaGetSymbolAddress((void**)&spatio, g_spatio);

    cudaFuncSetAttribute(gemm_bf<0,1,0,0,1>, cudaFuncAttributeMaxDynamicSharedMemorySize, SMEM_TOTAL);
    cudaFuncSetAttribute(gemm_bf<1,1,0,0,0>, cudaFuncAttributeMaxDynamicSharedMemorySize, SMEM_TOTAL);
    cudaFuncSetAttribute(gemm_bf<0,0,0,0,1>, cudaFuncAttributeMaxDynamicSharedMemorySize, SMEM_TOTAL);
    cudaFuncSetAttribute(gemm_bf<0,1,0,0,0>, cudaFuncAttributeMaxDynamicSharedMemorySize, SMEM_TOTAL);
    cudaFuncSetAttribute(gemm_bf<0,1,0,1,1>, cudaFuncAttributeMaxDynamicSharedMemorySize, SMEM_TOTAL);
    cudaFuncSetAttribute(gemm_bf<0,0,1,0,0>, cudaFuncAttributeMaxDynamicSharedMemorySize, SMEM_TOTAL);

    const long SCHW = (long)CC * CHW;
    const long SATT = (long)CHW * CHW;
    const long WSZ  = (long)CC * CC;

    dim3 gridConv(CC / 128, CHW / 128, CBT);     // (4, 8, 20)
    dim3 gridScores(CHW / 128, CHW / 128, CBT);  // (8, 8, 20)
    dim3 thr(256);

    // 0) weights -> bf16 (order: wq wk wv wo wqt wkt wvt wot)
    cvt_weights<<<dim3(CC * CC / 256, 8), thr>>>(wq, wk, wv, wo, wqt, wkt, wvt, wot, wb);
    const __nv_bfloat16 *wqb = wb, *wkb = wb + WSZ, *wvb = wb + 2 * WSZ, *wob = wb + 3 * WSZ,
                        *wqtb = wb + 4 * WSZ, *wktb = wb + 5 * WSZ, *wvtb = wb + 6 * WSZ, *wotb = wb + 7 * WSZ;

    // 1) spatial GroupNorm -> bf16
    groupnorm_kernel<<<CBT * CG, thr>>>(x, hnb, gamma_s, beta_s);

    // 2) q/k/v projections: A=W [m][k], B=hn [k][n]; bf16 out
    gemm_bf<0,1,0,0,1><<<gridConv, thr, SMEM_TOTAL>>>(wqb, hnb, qb, bq, nullptr, CHW, CC, CC, CHW,
                                0, SCHW, SCHW, 0, 1.f);
    gemm_bf<0,1,0,0,1><<<gridConv, thr, SMEM_TOTAL>>>(wkb, hnb, kb, bk, nullptr, CHW, CC, CC, CHW,
                                0, SCHW, SCHW, 0, 1.f);
    gemm_bf<0,1,0,0,1><<<gridConv, thr, SMEM_TOTAL>>>(wvb, hnb, vb, bv, nullptr, CHW, CC, CC, CHW,
                                0, SCHW, SCHW, 0, 1.f);

    // 3) scores = scale * Q^T K : A=q [k][m], B=k [k][n]; fp32 out
    gemm_bf<1,1,0,0,0><<<gridScores, thr, SMEM_TOTAL>>>(qb, kb, attf, nullptr, nullptr, CHW, CC, CHW, CHW,
                                  SCHW, SCHW, SATT, 0, SCALE);

    // 4) softmax over keys -> bf16
    softmax_kernel<<<CBT * CHW, thr>>>(attf, attb);

    // 5) hsp = V * Att^T : A=v [m][k], B=att [n][k]; bf16 out
    gemm_bf<0,0,0,0,1><<<gridConv, thr, SMEM_TOTAL>>>(vb, attb, hspb, nullptr, nullptr, CHW, CHW, CHW, CHW,
                                SCHW, SATT, SCHW, 0, 1.f);

    // 6) spatio = x + Wo*hsp + bo; fp32 out
    gemm_bf<0,1,0,0,0><<<gridConv, thr, SMEM_TOTAL>>>(wob, hspb, spatio, bo, x, CHW, CC, CC, CHW,
                                0, SCHW, SCHW, SCHW, 1.f);

    // 7) temporal GroupNorm -> bf16
    groupnorm_kernel<<<CBT * CG, thr>>>(spatio, hnb, gamma_t, beta_t);

    // 8) temporal q/k/v projections, store pixel-major [b][p][t][c] bf16
    gemm_bf<0,1,0,1,1><<<gridConv, thr, SMEM_TOTAL>>>(wqtb, hnb, qb, bqt, nullptr, CHW, CC, CC, CHW,
                                0, SCHW, 0, 0, 1.f);
    gemm_bf<0,1,0,1,1><<<gridConv, thr, SMEM_TOTAL>>>(wktb, hnb, kb, bkt, nullptr, CHW, CC, CC, CHW,
                                0, SCHW, 0, 0, 1.f);
    gemm_bf<0,1,0,1,1><<<gridConv, thr, SMEM_TOTAL>>>(wvtb, hnb, vb, bvt, nullptr, CHW, CC, CC, CHW,
                                0, SCHW, 0, 0, 1.f);

    // 9) per-pixel temporal attention (htp into hspb, pixel-major bf16)
    temporal_attn_kernel<<<CB * CHW, thr>>>(qb, kb, vb, hspb);

    // 10) out = x + Wot*htp + bot : B=[n][k] rows via pixel-major (ldb=TTC); fp32 out
    gemm_bf<0,0,1,0,0><<<gridConv, thr, SMEM_TOTAL>>>(wotb, hspb, out, bot, x, CHW, CC, CC, TTC,
                                0, 0, SCHW, SCHW, 1.f);
}